// round 14
// baseline (speedup 1.0000x reference)
#include <cuda_runtime.h>
#include <math.h>
#include <stdint.h>

#define NMAX 50000
#define EMAX 800000

// ---------------- scratch (static device globals) ----------------------------
__device__ float g_h1[NMAX * 256];
__device__ float g_out1[NMAX * 256];
__device__ float g_h2[NMAX * 128];
__device__ float g_als1[NMAX * 8];
__device__ float g_ald1[NMAX * 8];
__device__ float g_als2[NMAX];
__device__ float g_ald2[NMAX];
__device__ float g_rae[48];
__device__ int   g_off[NMAX + 1];
__device__ int   g_cur[NMAX];
__device__ int   g_bsum[64];
__device__ int   g_csr_pack[EMAX];     // src | (type << 20)

// ---------------- init (also zeroes the layer-2 logit accumulators) --------------
__global__ void init_kernel(int Nn) {
    int i = blockIdx.x * blockDim.x + threadIdx.x;
    if (i < Nn) {
        g_cur[i] = 0;
        g_als2[i] = 0.f;
        g_ald2[i] = 0.f;
    }
}

// ---------------- collapse edge-feature attention -------------------------------
__global__ void prep_kernel(const float* __restrict__ We1,
                            const float* __restrict__ atte,
                            const float* __restrict__ rel_emb) {
    __shared__ float sve[64 * 8];
    int t = threadIdx.x;                 // 512 threads
    int d = t >> 3, h = t & 7;
    float s = 0.f;
    #pragma unroll
    for (int c = 0; c < 32; ++c)
        s += We1[d * 256 + h * 32 + c] * atte[h * 32 + c];
    sve[t] = s;
    __syncthreads();
    if (t < 48) {
        int r = t >> 3, hh = t & 7;
        float acc = 0.f;
        #pragma unroll
        for (int dd = 0; dd < 64; ++dd)
            acc += rel_emb[r * 64 + dd] * sve[dd * 8 + hh];
        g_rae[t] = acc;
    }
}

// ---------------- CSR build ------------------------------------------------------
__global__ void hist_kernel(const int* __restrict__ dst0, int E) {
    int e = blockIdx.x * blockDim.x + threadIdx.x;
    if (e < E) atomicAdd(&g_cur[dst0[e]], 1);
}

__global__ void scan_part_kernel(int Nn) {
    __shared__ int sh[1024];
    int t = threadIdx.x;
    int i = blockIdx.x * 1024 + t;
    int v = (i < Nn) ? g_cur[i] : 0;
    sh[t] = v;
    __syncthreads();
    #pragma unroll
    for (int o = 1; o < 1024; o <<= 1) {
        int add = (t >= o) ? sh[t - o] : 0;
        __syncthreads();
        sh[t] += add;
        __syncthreads();
    }
    if (i < Nn) g_off[i] = sh[t] - v;
    if (t == 1023) g_bsum[blockIdx.x] = sh[1023];
}

__global__ void scan_tops_kernel(int nb) {
    __shared__ int sh[64];
    int t = threadIdx.x;
    int v = (t < nb) ? g_bsum[t] : 0;
    sh[t] = v;
    __syncthreads();
    #pragma unroll
    for (int o = 1; o < 64; o <<= 1) {
        int add = (t >= o) ? sh[t - o] : 0;
        __syncthreads();
        sh[t] += add;
        __syncthreads();
    }
    g_bsum[t] = sh[t] - v;
}

__global__ void scan_add_kernel(int Nn, int E) {
    int i = blockIdx.x * blockDim.x + threadIdx.x;
    if (i < Nn) {
        int o = g_off[i] + g_bsum[i >> 10];
        g_off[i] = o;
        g_cur[i] = o;
    }
    if (i == 0) g_off[Nn] = E;
}

__global__ void scatter_kernel(const int* __restrict__ src0,
                               const int* __restrict__ dst0,
                               const int* __restrict__ etype, int E) {
    int e = blockIdx.x * blockDim.x + threadIdx.x;
    if (e >= E) return;
    int d = dst0[e];
    int pos = atomicAdd(&g_cur[d], 1);
    g_csr_pack[pos] = src0[e] | (etype[e] << 20);
}

// ---------------- TF32 tensor-core GEMM (STAGES-deep cp.async) + fused epilogues --
__device__ __forceinline__ uint32_t f2tf32(float x) {
    uint32_t r;
    asm("cvt.rna.tf32.f32 %0, %1;" : "=r"(r) : "f"(x));
    return r;
}

__device__ __forceinline__ void mma_tf32(float* c, const uint32_t* a, const uint32_t* b) {
    asm volatile(
        "mma.sync.aligned.m16n8k8.row.col.f32.tf32.tf32.f32 "
        "{%0,%1,%2,%3}, {%4,%5,%6,%7}, {%8,%9}, {%0,%1,%2,%3};"
        : "+f"(c[0]), "+f"(c[1]), "+f"(c[2]), "+f"(c[3])
        : "r"(a[0]), "r"(a[1]), "r"(a[2]), "r"(a[3]), "r"(b[0]), "r"(b[1]));
}

__device__ __forceinline__ uint32_t smem_u32(const void* p) {
    return (uint32_t)__cvta_generic_to_shared(p);
}

#define AS_LD 36
// BN-templated GEMM: BM=128, 8 warps as 2x4, warp tile 64 x (BN/4).
// BS_LD: stride mod 32 == 8 -> conflict-free b-frag LDS.
// FUSE_MODE 0: none; 1: layer-1 per-head logits; 2: layer-2 logits via atomicAdd.
template <int BN, int FUSE_MODE, int STAGES>
__global__ void __launch_bounds__(256, (BN == 128) ? 2 : 1)
gemm_tf32_kernel(const float* __restrict__ A, const float* __restrict__ B,
                 float* __restrict__ C, int M, int N, int K,
                 const float* __restrict__ attn_s, const float* __restrict__ attn_d,
                 float* __restrict__ out_als, float* __restrict__ out_ald) {
    constexpr int BS_LD = BN + 8;
    constexpr int WN = BN / 4;
    constexpr int NT = WN / 8;
    constexpr int NHEAD = WN / 32;
    constexpr int A_STG = 128 * AS_LD;
    constexpr int B_STG = 32 * BS_LD;

    extern __shared__ float dynsmem[];
    float* AsBase = dynsmem;                           // STAGES * A_STG
    float* BsBase = dynsmem + STAGES * A_STG;          // STAGES * B_STG

    const int tid = threadIdx.x;
    const int lane = tid & 31, wid = tid >> 5;
    const int wm = (wid >> 2) * 64;
    const int wn = (wid & 3) * WN;
    const int bn0 = blockIdx.x * BN;
    const int bm0 = blockIdx.y * 128;

    const int a_r = tid >> 3;
    const int a_c = (tid & 7) * 4;
    const int b_r = tid / (BN / 4);
    const int b_c = (tid % (BN / 4)) * 4;
    constexpr int B_ROWS_ITER = 1024 / BN;
    constexpr int B_ITERS = 32 / B_ROWS_ITER;

    float acc[4][NT][4];
    #pragma unroll
    for (int i = 0; i < 4; ++i)
        #pragma unroll
        for (int j = 0; j < NT; ++j)
            #pragma unroll
            for (int k = 0; k < 4; ++k) acc[i][j][k] = 0.f;

    const int nk = K >> 5;

    auto load_stage = [&](int kt, int buf) {
        const int k0 = kt * 32;
        float* As = AsBase + buf * A_STG;
        float* Bs = BsBase + buf * B_STG;
        #pragma unroll
        for (int i = 0; i < 4; ++i) {
            int row = a_r + 32 * i;
            int grow = bm0 + row;
            int ok = (grow < M);
            const float* src = A + (size_t)(ok ? grow : 0) * K + k0 + a_c;
            uint32_t dst = smem_u32(&As[row * AS_LD + a_c]);
            int nb = ok ? 16 : 0;
            asm volatile("cp.async.ca.shared.global [%0], [%1], 16, %2;"
                         :: "r"(dst), "l"(src), "r"(nb));
        }
        #pragma unroll
        for (int i = 0; i < B_ITERS; ++i) {
            int row = b_r + B_ROWS_ITER * i;
            const float* src = B + (size_t)(k0 + row) * N + bn0 + b_c;
            uint32_t dst = smem_u32(&Bs[row * BS_LD + b_c]);
            asm volatile("cp.async.ca.shared.global [%0], [%1], 16;"
                         :: "r"(dst), "l"(src));
        }
        asm volatile("cp.async.commit_group;");
    };

    load_stage(0, 0);
    if (STAGES >= 3 && nk > 1) load_stage(1, 1);

    for (int kt = 0; kt < nk; ++kt) {
        if (STAGES == 2) {
            const int buf = kt & 1;
            if (kt + 1 < nk) load_stage(kt + 1, buf ^ 1);
            else asm volatile("cp.async.commit_group;");
            asm volatile("cp.async.wait_group 1;");
            __syncthreads();
            // compute below uses buf
        } else {
            // 3-stage: wait for kt (allow kt+1 in flight), then sync, then issue kt+2
            if (kt + 1 < nk) asm volatile("cp.async.wait_group 1;");
            else             asm volatile("cp.async.wait_group 0;");
            __syncthreads();
            if (kt + 2 < nk) {
                int nbuf = kt + 2;
                nbuf = nbuf % 3;
                load_stage(kt + 2, nbuf);
            }
        }

        const int buf = (STAGES == 2) ? (kt & 1) : (kt % 3);
        const float* as = AsBase + buf * A_STG;
        const float* bs = BsBase + buf * B_STG;
        #pragma unroll
        for (int kk = 0; kk < 4; ++kk) {
            const int kb = kk * 8;
            uint32_t afrag[4][4], bfrag[NT][2];
            #pragma unroll
            for (int mt = 0; mt < 4; ++mt) {
                int r0 = wm + mt * 16 + (lane >> 2);
                int c0 = kb + (lane & 3);
                afrag[mt][0] = f2tf32(as[r0 * AS_LD + c0]);
                afrag[mt][1] = f2tf32(as[(r0 + 8) * AS_LD + c0]);
                afrag[mt][2] = f2tf32(as[r0 * AS_LD + c0 + 4]);
                afrag[mt][3] = f2tf32(as[(r0 + 8) * AS_LD + c0 + 4]);
            }
            #pragma unroll
            for (int nt = 0; nt < NT; ++nt) {
                int n0 = wn + nt * 8 + (lane >> 2);
                int kr = kb + (lane & 3);
                bfrag[nt][0] = f2tf32(bs[kr * BS_LD + n0]);
                bfrag[nt][1] = f2tf32(bs[(kr + 4) * BS_LD + n0]);
            }
            #pragma unroll
            for (int mt = 0; mt < 4; ++mt)
                #pragma unroll
                for (int nt = 0; nt < NT; ++nt)
                    mma_tf32(acc[mt][nt], afrag[mt], bfrag[nt]);
        }
        if (STAGES == 2) __syncthreads();
    }

    // ---- store C ----
    #pragma unroll
    for (int mt = 0; mt < 4; ++mt) {
        int row0 = bm0 + wm + mt * 16 + (lane >> 2);
        #pragma unroll
        for (int nt = 0; nt < NT; ++nt) {
            int col0 = bn0 + wn + nt * 8 + (lane & 3) * 2;
            if (row0 < M)
                *reinterpret_cast<float2*>(C + (size_t)row0 * N + col0) =
                    make_float2(acc[mt][nt][0], acc[mt][nt][1]);
            if (row0 + 8 < M)
                *reinterpret_cast<float2*>(C + (size_t)(row0 + 8) * N + col0) =
                    make_float2(acc[mt][nt][2], acc[mt][nt][3]);
        }
    }

    // ---- fused attention-logit epilogues ----
    if constexpr (FUSE_MODE == 1) {
        float asv[NT][2], adv[NT][2];
        #pragma unroll
        for (int nt = 0; nt < NT; ++nt) {
            int col = bn0 + wn + nt * 8 + (lane & 3) * 2;
            asv[nt][0] = attn_s[col];     asv[nt][1] = attn_s[col + 1];
            adv[nt][0] = attn_d[col];     adv[nt][1] = attn_d[col + 1];
        }
        #pragma unroll
        for (int mt = 0; mt < 4; ++mt) {
            #pragma unroll
            for (int hh = 0; hh < NHEAD; ++hh) {
                float slo = 0.f, shi = 0.f, dlo = 0.f, dhi = 0.f;
                #pragma unroll
                for (int q = 0; q < 4; ++q) {
                    int nt = hh * 4 + q;
                    slo += acc[mt][nt][0] * asv[nt][0] + acc[mt][nt][1] * asv[nt][1];
                    shi += acc[mt][nt][2] * asv[nt][0] + acc[mt][nt][3] * asv[nt][1];
                    dlo += acc[mt][nt][0] * adv[nt][0] + acc[mt][nt][1] * adv[nt][1];
                    dhi += acc[mt][nt][2] * adv[nt][0] + acc[mt][nt][3] * adv[nt][1];
                }
                #pragma unroll
                for (int o = 1; o <= 2; o <<= 1) {
                    slo += __shfl_xor_sync(0xffffffffu, slo, o);
                    shi += __shfl_xor_sync(0xffffffffu, shi, o);
                    dlo += __shfl_xor_sync(0xffffffffu, dlo, o);
                    dhi += __shfl_xor_sync(0xffffffffu, dhi, o);
                }
                if ((lane & 3) == 0) {
                    int head = (bn0 + wn) / 32 + hh;
                    int row0 = bm0 + wm + mt * 16 + (lane >> 2);
                    if (row0 < M) {
                        out_als[row0 * 8 + head] = slo;
                        out_ald[row0 * 8 + head] = dlo;
                    }
                    if (row0 + 8 < M) {
                        out_als[(row0 + 8) * 8 + head] = shi;
                        out_ald[(row0 + 8) * 8 + head] = dhi;
                    }
                }
            }
        }
    }
    if constexpr (FUSE_MODE == 2) {
        float asv[NT][2], adv[NT][2];
        #pragma unroll
        for (int nt = 0; nt < NT; ++nt) {
            int col = bn0 + wn + nt * 8 + (lane & 3) * 2;
            asv[nt][0] = attn_s[col];     asv[nt][1] = attn_s[col + 1];
            adv[nt][0] = attn_d[col];     adv[nt][1] = attn_d[col + 1];
        }
        #pragma unroll
        for (int mt = 0; mt < 4; ++mt) {
            float slo = 0.f, shi = 0.f, dlo = 0.f, dhi = 0.f;
            #pragma unroll
            for (int nt = 0; nt < NT; ++nt) {
                slo += acc[mt][nt][0] * asv[nt][0] + acc[mt][nt][1] * asv[nt][1];
                shi += acc[mt][nt][2] * asv[nt][0] + acc[mt][nt][3] * asv[nt][1];
                dlo += acc[mt][nt][0] * adv[nt][0] + acc[mt][nt][1] * adv[nt][1];
                dhi += acc[mt][nt][2] * adv[nt][0] + acc[mt][nt][3] * adv[nt][1];
            }
            #pragma unroll
            for (int o = 1; o <= 2; o <<= 1) {
                slo += __shfl_xor_sync(0xffffffffu, slo, o);
                shi += __shfl_xor_sync(0xffffffffu, shi, o);
                dlo += __shfl_xor_sync(0xffffffffu, dlo, o);
                dhi += __shfl_xor_sync(0xffffffffu, dhi, o);
            }
            if ((lane & 3) == 0) {
                int row0 = bm0 + wm + mt * 16 + (lane >> 2);
                if (row0 < M) {
                    atomicAdd(&out_als[row0], slo);
                    atomicAdd(&out_ald[row0], dlo);
                }
                if (row0 + 8 < M) {
                    atomicAdd(&out_als[row0 + 8], shi);
                    atomicAdd(&out_ald[row0 + 8], dhi);
                }
            }
        }
    }
}

#define G1_SMEM ((3 * 128 * AS_LD + 3 * 32 * (256 + 8)) * 4)
#define G2_SMEM ((2 * 128 * AS_LD + 2 * 32 * (128 + 8)) * 4)

// ---------------- layer-1: warp-per-node softmax+aggregate+bias+LN+ELU -----------
__global__ void __launch_bounds__(256)
gat1_warp_kernel(const float* __restrict__ b, const float* __restrict__ g,
                 const float* __restrict__ beta, int Nn) {
    __shared__ float sh_rae[48];
    const int t = threadIdx.x;
    if (t < 48) sh_rae[t] = g_rae[t];
    __syncthreads();

    const int d = blockIdx.x * 8 + (t >> 5);
    if (d >= Nn) return;
    const int lane = t & 31;
    const int hl = lane >> 2;

    const int beg = g_off[d], end = g_off[d + 1];
    const float aldl = g_ald1[d * 8 + hl];

    float acc[8] = {0.f, 0.f, 0.f, 0.f, 0.f, 0.f, 0.f, 0.f};
    float den = 0.f, sumrae = 0.f;

    #pragma unroll 2
    for (int e = beg; e < end; ++e) {
        int p = g_csr_pack[e];
        int s = p & 0xFFFFF, r = p >> 20;
        float rv = sh_rae[r * 8 + hl];
        float a = g_als1[s * 8 + hl] + aldl + rv;
        a = a > 0.f ? a : 0.2f * a;
        float ex = __expf(a);
        den += ex;
        sumrae += rv;
        const float4* hp = reinterpret_cast<const float4*>(g_h1 + (size_t)s * 256);
        float4 v0 = hp[lane * 2], v1 = hp[lane * 2 + 1];
        acc[0] += ex * v0.x; acc[1] += ex * v0.y;
        acc[2] += ex * v0.z; acc[3] += ex * v0.w;
        acc[4] += ex * v1.x; acc[5] += ex * v1.y;
        acc[6] += ex * v1.z; acc[7] += ex * v1.w;
    }

    float deg = (float)(end - beg);
    float asf = g_als1[d * 8 + hl] + aldl + sumrae / fmaxf(deg, 1.f);
    asf = asf > 0.f ? asf : 0.2f * asf;
    float exs = __expf(asf);
    den += exs;
    {
        const float4* hp = reinterpret_cast<const float4*>(g_h1 + (size_t)d * 256);
        float4 v0 = hp[lane * 2], v1 = hp[lane * 2 + 1];
        acc[0] += exs * v0.x; acc[1] += exs * v0.y;
        acc[2] += exs * v0.z; acc[3] += exs * v0.w;
        acc[4] += exs * v1.x; acc[5] += exs * v1.y;
        acc[6] += exs * v1.z; acc[7] += exs * v1.w;
    }

    float inv = 1.f / (den + 1e-16f);
    const float4* bp = reinterpret_cast<const float4*>(b);
    float4 b0 = bp[lane * 2], b1 = bp[lane * 2 + 1];
    float v[8];
    v[0] = acc[0] * inv + b0.x; v[1] = acc[1] * inv + b0.y;
    v[2] = acc[2] * inv + b0.z; v[3] = acc[3] * inv + b0.w;
    v[4] = acc[4] * inv + b1.x; v[5] = acc[5] * inv + b1.y;
    v[6] = acc[6] * inv + b1.z; v[7] = acc[7] * inv + b1.w;

    float s1 = 0.f, s2 = 0.f;
    #pragma unroll
    for (int k = 0; k < 8; ++k) { s1 += v[k]; s2 += v[k] * v[k]; }
    #pragma unroll
    for (int o = 16; o; o >>= 1) {
        s1 += __shfl_xor_sync(0xffffffffu, s1, o);
        s2 += __shfl_xor_sync(0xffffffffu, s2, o);
    }
    float m = s1 * (1.f / 256.f);
    float var = s2 * (1.f / 256.f) - m * m;
    float rstd = rsqrtf(var + 1e-5f);

    const float4* gp = reinterpret_cast<const float4*>(g);
    const float4* betap = reinterpret_cast<const float4*>(beta);
    float4 g0 = gp[lane * 2], g1v = gp[lane * 2 + 1];
    float4 be0 = betap[lane * 2], be1 = betap[lane * 2 + 1];
    float gg[8] = {g0.x, g0.y, g0.z, g0.w, g1v.x, g1v.y, g1v.z, g1v.w};
    float bb[8] = {be0.x, be0.y, be0.z, be0.w, be1.x, be1.y, be1.z, be1.w};
    float y[8];
    #pragma unroll
    for (int k = 0; k < 8; ++k) {
        float yy = (v[k] - m) * rstd * gg[k] + bb[k];
        y[k] = yy > 0.f ? yy : expm1f(yy);
    }
    float4* op = reinterpret_cast<float4*>(g_out1 + (size_t)d * 256);
    op[lane * 2]     = make_float4(y[0], y[1], y[2], y[3]);
    op[lane * 2 + 1] = make_float4(y[4], y[5], y[6], y[7]);
}

// ---------------- layer-2: warp-per-node softmax+aggregate+bias+LN ---------------
__global__ void __launch_bounds__(256)
gat2_warp_kernel(const float* __restrict__ b, const float* __restrict__ g,
                 const float* __restrict__ beta, float* __restrict__ out, int Nn) {
    const int t = threadIdx.x;
    const int d = blockIdx.x * 8 + (t >> 5);
    if (d >= Nn) return;
    const int lane = t & 31;

    const int beg = g_off[d], end = g_off[d + 1];
    const float ald = g_ald2[d];

    float acc[4] = {0.f, 0.f, 0.f, 0.f};
    float den = 0.f;

    #pragma unroll 2
    for (int e = beg; e < end; ++e) {
        int s = g_csr_pack[e] & 0xFFFFF;
        float a = g_als2[s] + ald;
        a = a > 0.f ? a : 0.2f * a;
        float ex = __expf(a);
        den += ex;
        float4 v = reinterpret_cast<const float4*>(g_h2 + (size_t)s * 128)[lane];
        acc[0] += ex * v.x; acc[1] += ex * v.y;
        acc[2] += ex * v.z; acc[3] += ex * v.w;
    }

    float asf = g_als2[d] + ald;
    asf = asf > 0.f ? asf : 0.2f * asf;
    float exs = __expf(asf);
    den += exs;
    {
        float4 v = reinterpret_cast<const float4*>(g_h2 + (size_t)d * 128)[lane];
        acc[0] += exs * v.x; acc[1] += exs * v.y;
        acc[2] += exs * v.z; acc[3] += exs * v.w;
    }

    float inv = 1.f / (den + 1e-16f);
    float4 bv = reinterpret_cast<const float4*>(b)[lane];
    float v[4];
    v[0] = acc[0] * inv + bv.x; v[1] = acc[1] * inv + bv.y;
    v[2] = acc[2] * inv + bv.z; v[3] = acc[3] * inv + bv.w;

    float s1 = 0.f, s2 = 0.f;
    #pragma unroll
    for (int k = 0; k < 4; ++k) { s1 += v[k]; s2 += v[k] * v[k]; }
    #pragma unroll
    for (int o = 16; o; o >>= 1) {
        s1 += __shfl_xor_sync(0xffffffffu, s1, o);
        s2 += __shfl_xor_sync(0xffffffffu, s2, o);
    }
    float m = s1 * (1.f / 128.f);
    float var = s2 * (1.f / 128.f) - m * m;
    float rstd = rsqrtf(var + 1e-5f);

    float4 gv = reinterpret_cast<const float4*>(g)[lane];
    float4 bev = reinterpret_cast<const float4*>(beta)[lane];
    float4 o4;
    o4.x = (v[0] - m) * rstd * gv.x + bev.x;
    o4.y = (v[1] - m) * rstd * gv.y + bev.y;
    o4.z = (v[2] - m) * rstd * gv.z + bev.z;
    o4.w = (v[3] - m) * rstd * gv.w + bev.w;
    reinterpret_cast<float4*>(out + (size_t)d * 128)[lane] = o4;
}

// ---------------- launch -----------------------------------------------------------
extern "C" void kernel_launch(void* const* d_in, const int* in_sizes, int n_in,
                              void* d_out, int out_size) {
    const float* x       = (const float*)d_in[0];
    const int*   ei      = (const int*)d_in[1];
    const int*   etype   = (const int*)d_in[2];
    const float* rel_emb = (const float*)d_in[3];
    const float* W1      = (const float*)d_in[4];
    const float* as1     = (const float*)d_in[5];
    const float* ad1     = (const float*)d_in[6];
    const float* We1     = (const float*)d_in[7];
    const float* ae1     = (const float*)d_in[8];
    const float* b1      = (const float*)d_in[9];
    const float* g1      = (const float*)d_in[10];
    const float* beta1   = (const float*)d_in[11];
    const float* W2      = (const float*)d_in[12];
    const float* as2     = (const float*)d_in[13];
    const float* ad2     = (const float*)d_in[14];
    const float* b2      = (const float*)d_in[15];
    const float* g2      = (const float*)d_in[16];
    const float* beta2   = (const float*)d_in[17];
    float* out = (float*)d_out;

    const int E = in_sizes[2];
    const int Nn = in_sizes[0] / 768;
    const int* src0 = ei;
    const int* dst0 = ei + E;
    const int nb = (Nn + 1023) / 1024;
    const int nm = (Nn + 127) / 128;

    float *ph1, *pout1, *ph2, *pals1, *pald1, *pals2, *pald2;
    cudaGetSymbolAddress((void**)&ph1, g_h1);
    cudaGetSymbolAddress((void**)&pout1, g_out1);
    cudaGetSymbolAddress((void**)&ph2, g_h2);
    cudaGetSymbolAddress((void**)&pals1, g_als1);
    cudaGetSymbolAddress((void**)&pald1, g_ald1);
    cudaGetSymbolAddress((void**)&pals2, g_als2);
    cudaGetSymbolAddress((void**)&pald2, g_ald2);

    static cudaStream_t s_side = nullptr;
    static cudaEvent_t ev_fork = nullptr, ev_join = nullptr;
    if (!s_side) {
        cudaFuncSetAttribute(gemm_tf32_kernel<256, 1, 3>,
                             cudaFuncAttributeMaxDynamicSharedMemorySize, G1_SMEM);
        cudaFuncSetAttribute(gemm_tf32_kernel<128, 2, 2>,
                             cudaFuncAttributeMaxDynamicSharedMemorySize, G2_SMEM);
        cudaStreamCreateWithFlags(&s_side, cudaStreamNonBlocking);
        cudaEventCreateWithFlags(&ev_fork, cudaEventDisableTiming);
        cudaEventCreateWithFlags(&ev_join, cudaEventDisableTiming);
    }

    // ---- fork: CSR build + prep on side stream, GEMM1 on main stream ----
    cudaEventRecord(ev_fork, 0);
    cudaStreamWaitEvent(s_side, ev_fork, 0);

    init_kernel<<<(Nn + 255) / 256, 256, 0, s_side>>>(Nn);
    prep_kernel<<<1, 512, 0, s_side>>>(We1, ae1, rel_emb);
    hist_kernel<<<(E + 255) / 256, 256, 0, s_side>>>(dst0, E);
    scan_part_kernel<<<nb, 1024, 0, s_side>>>(Nn);
    scan_tops_kernel<<<1, 64, 0, s_side>>>(nb);
    scan_add_kernel<<<(Nn + 255) / 256, 256, 0, s_side>>>(Nn, E);
    scatter_kernel<<<(E + 255) / 256, 256, 0, s_side>>>(src0, dst0, etype, E);
    cudaEventRecord(ev_join, s_side);

    // GEMM1: h1 = x @ W1  [Nn,768]x[768,256], BN=256, 3-stage, fused attn1
    {
        dim3 grid(1, nm);
        gemm_tf32_kernel<256, 1, 3><<<grid, 256, G1_SMEM>>>(
            x, W1, ph1, Nn, 256, 768, as1, ad1, pals1, pald1);
    }

    // ---- join ----
    cudaStreamWaitEvent(0, ev_join, 0);

    gat1_warp_kernel<<<(Nn + 7) / 8, 256>>>(b1, g1, beta1, Nn);

    // GEMM2: h2 = out1 @ W2  [Nn,256]x[256,128], 2-stage occ-2, fused attn2
    {
        dim3 grid(1, nm);
        gemm_tf32_kernel<128, 2, 2><<<grid, 256, G2_SMEM>>>(
            pout1, W2, ph2, Nn, 128, 256, as2, ad2, pals2, pald2);
    }
    gat2_warp_kernel<<<(Nn + 7) / 8, 256>>>(b2, g2, beta2, out, Nn);
}

// round 15
// speedup vs baseline: 1.0415x; 1.0415x over previous
#include <cuda_runtime.h>
#include <cuda_fp16.h>
#include <math.h>
#include <stdint.h>

#define NMAX 50000
#define EMAX 800000

// ---------------- scratch (static device globals) ----------------------------
__device__ unsigned int g_h1h[NMAX * 128];   // h1 as half2 pairs (256 ch)
__device__ unsigned int g_h2h[NMAX * 64];    // h2 as half2 pairs (128 ch)
__device__ float g_out1[NMAX * 256];
__device__ float g_als1[NMAX * 8];
__device__ float g_ald1[NMAX * 8];
__device__ float g_als2[NMAX];
__device__ float g_ald2[NMAX];
__device__ float g_rae[48];
__device__ int   g_off[NMAX + 1];
__device__ int   g_cur[NMAX];
__device__ int   g_bsum[64];
__device__ int   g_csr_pack[EMAX];     // src | (type << 20)

// ---------------- init (also zeroes the layer-2 logit accumulators) --------------
__global__ void init_kernel(int Nn) {
    int i = blockIdx.x * blockDim.x + threadIdx.x;
    if (i < Nn) {
        g_cur[i] = 0;
        g_als2[i] = 0.f;
        g_ald2[i] = 0.f;
    }
}

// ---------------- collapse edge-feature attention -------------------------------
__global__ void prep_kernel(const float* __restrict__ We1,
                            const float* __restrict__ atte,
                            const float* __restrict__ rel_emb) {
    __shared__ float sve[64 * 8];
    int t = threadIdx.x;                 // 512 threads
    int d = t >> 3, h = t & 7;
    float s = 0.f;
    #pragma unroll
    for (int c = 0; c < 32; ++c)
        s += We1[d * 256 + h * 32 + c] * atte[h * 32 + c];
    sve[t] = s;
    __syncthreads();
    if (t < 48) {
        int r = t >> 3, hh = t & 7;
        float acc = 0.f;
        #pragma unroll
        for (int dd = 0; dd < 64; ++dd)
            acc += rel_emb[r * 64 + dd] * sve[dd * 8 + hh];
        g_rae[t] = acc;
    }
}

// ---------------- CSR build ------------------------------------------------------
__global__ void hist_kernel(const int* __restrict__ dst0, int E) {
    int e = blockIdx.x * blockDim.x + threadIdx.x;
    if (e < E) atomicAdd(&g_cur[dst0[e]], 1);
}

__global__ void scan_part_kernel(int Nn) {
    __shared__ int sh[1024];
    int t = threadIdx.x;
    int i = blockIdx.x * 1024 + t;
    int v = (i < Nn) ? g_cur[i] : 0;
    sh[t] = v;
    __syncthreads();
    #pragma unroll
    for (int o = 1; o < 1024; o <<= 1) {
        int add = (t >= o) ? sh[t - o] : 0;
        __syncthreads();
        sh[t] += add;
        __syncthreads();
    }
    if (i < Nn) g_off[i] = sh[t] - v;
    if (t == 1023) g_bsum[blockIdx.x] = sh[1023];
}

__global__ void scan_tops_kernel(int nb) {
    __shared__ int sh[64];
    int t = threadIdx.x;
    int v = (t < nb) ? g_bsum[t] : 0;
    sh[t] = v;
    __syncthreads();
    #pragma unroll
    for (int o = 1; o < 64; o <<= 1) {
        int add = (t >= o) ? sh[t - o] : 0;
        __syncthreads();
        sh[t] += add;
        __syncthreads();
    }
    g_bsum[t] = sh[t] - v;
}

__global__ void scan_add_kernel(int Nn, int E) {
    int i = blockIdx.x * blockDim.x + threadIdx.x;
    if (i < Nn) {
        int o = g_off[i] + g_bsum[i >> 10];
        g_off[i] = o;
        g_cur[i] = o;
    }
    if (i == 0) g_off[Nn] = E;
}

__global__ void scatter_kernel(const int* __restrict__ src0,
                               const int* __restrict__ dst0,
                               const int* __restrict__ etype, int E) {
    int e = blockIdx.x * blockDim.x + threadIdx.x;
    if (e >= E) return;
    int d = dst0[e];
    int pos = atomicAdd(&g_cur[d], 1);
    g_csr_pack[pos] = src0[e] | (etype[e] << 20);
}

// ---------------- TF32 tensor-core GEMM, half2 output + fused epilogues ----------
__device__ __forceinline__ uint32_t f2tf32(float x) {
    uint32_t r;
    asm("cvt.rna.tf32.f32 %0, %1;" : "=r"(r) : "f"(x));
    return r;
}

__device__ __forceinline__ void mma_tf32(float* c, const uint32_t* a, const uint32_t* b) {
    asm volatile(
        "mma.sync.aligned.m16n8k8.row.col.f32.tf32.tf32.f32 "
        "{%0,%1,%2,%3}, {%4,%5,%6,%7}, {%8,%9}, {%0,%1,%2,%3};"
        : "+f"(c[0]), "+f"(c[1]), "+f"(c[2]), "+f"(c[3])
        : "r"(a[0]), "r"(a[1]), "r"(a[2]), "r"(a[3]), "r"(b[0]), "r"(b[1]));
}

__device__ __forceinline__ uint32_t smem_u32(const void* p) {
    return (uint32_t)__cvta_generic_to_shared(p);
}

__device__ __forceinline__ unsigned int pack_h2(float a, float b) {
    __half2 h = __floats2half2_rn(a, b);
    return *reinterpret_cast<unsigned int*>(&h);
}

#define AS_LD 36
// BN-templated GEMM: BM=128, 8 warps as 2x4, warp tile 64 x (BN/4).
// Output written as half2 pairs into Ch (row stride N/2 uints).
// FUSE_MODE 1: layer-1 per-head logits; 2: layer-2 logits via atomicAdd.
template <int BN, int FUSE_MODE>
__global__ void __launch_bounds__(256, (BN == 128) ? 2 : 1)
gemm_tf32_kernel(const float* __restrict__ A, const float* __restrict__ B,
                 unsigned int* __restrict__ Ch, int M, int N, int K,
                 const float* __restrict__ attn_s, const float* __restrict__ attn_d,
                 float* __restrict__ out_als, float* __restrict__ out_ald) {
    constexpr int BS_LD = BN + 8;
    constexpr int WN = BN / 4;
    constexpr int NT = WN / 8;
    constexpr int NHEAD = WN / 32;

    extern __shared__ float dynsmem[];
    float* AsBase = dynsmem;
    float* BsBase = dynsmem + 2 * 128 * AS_LD;

    const int tid = threadIdx.x;
    const int lane = tid & 31, wid = tid >> 5;
    const int wm = (wid >> 2) * 64;
    const int wn = (wid & 3) * WN;
    const int bn0 = blockIdx.x * BN;
    const int bm0 = blockIdx.y * 128;

    const int a_r = tid >> 3;
    const int a_c = (tid & 7) * 4;
    const int b_r = tid / (BN / 4);
    const int b_c = (tid % (BN / 4)) * 4;
    constexpr int B_ROWS_ITER = 1024 / BN;
    constexpr int B_ITERS = 32 / B_ROWS_ITER;

    float acc[4][NT][4];
    #pragma unroll
    for (int i = 0; i < 4; ++i)
        #pragma unroll
        for (int j = 0; j < NT; ++j)
            #pragma unroll
            for (int k = 0; k < 4; ++k) acc[i][j][k] = 0.f;

    const int nk = K >> 5;

    auto load_stage = [&](int kt, int buf) {
        const int k0 = kt * 32;
        float* As = AsBase + buf * 128 * AS_LD;
        float* Bs = BsBase + buf * 32 * BS_LD;
        #pragma unroll
        for (int i = 0; i < 4; ++i) {
            int row = a_r + 32 * i;
            int grow = bm0 + row;
            int ok = (grow < M);
            const float* src = A + (size_t)(ok ? grow : 0) * K + k0 + a_c;
            uint32_t dst = smem_u32(&As[row * AS_LD + a_c]);
            int nb = ok ? 16 : 0;
            asm volatile("cp.async.ca.shared.global [%0], [%1], 16, %2;"
                         :: "r"(dst), "l"(src), "r"(nb));
        }
        #pragma unroll
        for (int i = 0; i < B_ITERS; ++i) {
            int row = b_r + B_ROWS_ITER * i;
            const float* src = B + (size_t)(k0 + row) * N + bn0 + b_c;
            uint32_t dst = smem_u32(&Bs[row * BS_LD + b_c]);
            asm volatile("cp.async.ca.shared.global [%0], [%1], 16;"
                         :: "r"(dst), "l"(src));
        }
        asm volatile("cp.async.commit_group;");
    };

    load_stage(0, 0);

    for (int kt = 0; kt < nk; ++kt) {
        const int buf = kt & 1;
        if (kt + 1 < nk) load_stage(kt + 1, buf ^ 1);
        else asm volatile("cp.async.commit_group;");
        asm volatile("cp.async.wait_group 1;");
        __syncthreads();

        const float* as = AsBase + buf * 128 * AS_LD;
        const float* bs = BsBase + buf * 32 * BS_LD;
        #pragma unroll
        for (int kk = 0; kk < 4; ++kk) {
            const int kb = kk * 8;
            uint32_t afrag[4][4], bfrag[NT][2];
            #pragma unroll
            for (int mt = 0; mt < 4; ++mt) {
                int r0 = wm + mt * 16 + (lane >> 2);
                int c0 = kb + (lane & 3);
                afrag[mt][0] = f2tf32(as[r0 * AS_LD + c0]);
                afrag[mt][1] = f2tf32(as[(r0 + 8) * AS_LD + c0]);
                afrag[mt][2] = f2tf32(as[r0 * AS_LD + c0 + 4]);
                afrag[mt][3] = f2tf32(as[(r0 + 8) * AS_LD + c0 + 4]);
            }
            #pragma unroll
            for (int nt = 0; nt < NT; ++nt) {
                int n0 = wn + nt * 8 + (lane >> 2);
                int kr = kb + (lane & 3);
                bfrag[nt][0] = f2tf32(bs[kr * BS_LD + n0]);
                bfrag[nt][1] = f2tf32(bs[(kr + 4) * BS_LD + n0]);
            }
            #pragma unroll
            for (int mt = 0; mt < 4; ++mt)
                #pragma unroll
                for (int nt = 0; nt < NT; ++nt)
                    mma_tf32(acc[mt][nt], afrag[mt], bfrag[nt]);
        }
        __syncthreads();
    }

    // ---- store C as half2 pairs ----
    const int NH = N / 2;
    #pragma unroll
    for (int mt = 0; mt < 4; ++mt) {
        int row0 = bm0 + wm + mt * 16 + (lane >> 2);
        #pragma unroll
        for (int nt = 0; nt < NT; ++nt) {
            int cp = (bn0 + wn + nt * 8 + (lane & 3) * 2) >> 1;   // half2 pair index
            if (row0 < M)
                Ch[(size_t)row0 * NH + cp] = pack_h2(acc[mt][nt][0], acc[mt][nt][1]);
            if (row0 + 8 < M)
                Ch[(size_t)(row0 + 8) * NH + cp] = pack_h2(acc[mt][nt][2], acc[mt][nt][3]);
        }
    }

    // ---- fused attention-logit epilogues (fp32 accumulators) ----
    if constexpr (FUSE_MODE == 1) {
        float asv[NT][2], adv[NT][2];
        #pragma unroll
        for (int nt = 0; nt < NT; ++nt) {
            int col = bn0 + wn + nt * 8 + (lane & 3) * 2;
            asv[nt][0] = attn_s[col];     asv[nt][1] = attn_s[col + 1];
            adv[nt][0] = attn_d[col];     adv[nt][1] = attn_d[col + 1];
        }
        #pragma unroll
        for (int mt = 0; mt < 4; ++mt) {
            #pragma unroll
            for (int hh = 0; hh < NHEAD; ++hh) {
                float slo = 0.f, shi = 0.f, dlo = 0.f, dhi = 0.f;
                #pragma unroll
                for (int q = 0; q < 4; ++q) {
                    int nt = hh * 4 + q;
                    slo += acc[mt][nt][0] * asv[nt][0] + acc[mt][nt][1] * asv[nt][1];
                    shi += acc[mt][nt][2] * asv[nt][0] + acc[mt][nt][3] * asv[nt][1];
                    dlo += acc[mt][nt][0] * adv[nt][0] + acc[mt][nt][1] * adv[nt][1];
                    dhi += acc[mt][nt][2] * adv[nt][0] + acc[mt][nt][3] * adv[nt][1];
                }
                #pragma unroll
                for (int o = 1; o <= 2; o <<= 1) {
                    slo += __shfl_xor_sync(0xffffffffu, slo, o);
                    shi += __shfl_xor_sync(0xffffffffu, shi, o);
                    dlo += __shfl_xor_sync(0xffffffffu, dlo, o);
                    dhi += __shfl_xor_sync(0xffffffffu, dhi, o);
                }
                if ((lane & 3) == 0) {
                    int head = (bn0 + wn) / 32 + hh;
                    int row0 = bm0 + wm + mt * 16 + (lane >> 2);
                    if (row0 < M) {
                        out_als[row0 * 8 + head] = slo;
                        out_ald[row0 * 8 + head] = dlo;
                    }
                    if (row0 + 8 < M) {
                        out_als[(row0 + 8) * 8 + head] = shi;
                        out_ald[(row0 + 8) * 8 + head] = dhi;
                    }
                }
            }
        }
    }
    if constexpr (FUSE_MODE == 2) {
        float asv[NT][2], adv[NT][2];
        #pragma unroll
        for (int nt = 0; nt < NT; ++nt) {
            int col = bn0 + wn + nt * 8 + (lane & 3) * 2;
            asv[nt][0] = attn_s[col];     asv[nt][1] = attn_s[col + 1];
            adv[nt][0] = attn_d[col];     adv[nt][1] = attn_d[col + 1];
        }
        #pragma unroll
        for (int mt = 0; mt < 4; ++mt) {
            float slo = 0.f, shi = 0.f, dlo = 0.f, dhi = 0.f;
            #pragma unroll
            for (int nt = 0; nt < NT; ++nt) {
                slo += acc[mt][nt][0] * asv[nt][0] + acc[mt][nt][1] * asv[nt][1];
                shi += acc[mt][nt][2] * asv[nt][0] + acc[mt][nt][3] * asv[nt][1];
                dlo += acc[mt][nt][0] * adv[nt][0] + acc[mt][nt][1] * adv[nt][1];
                dhi += acc[mt][nt][2] * adv[nt][0] + acc[mt][nt][3] * adv[nt][1];
            }
            #pragma unroll
            for (int o = 1; o <= 2; o <<= 1) {
                slo += __shfl_xor_sync(0xffffffffu, slo, o);
                shi += __shfl_xor_sync(0xffffffffu, shi, o);
                dlo += __shfl_xor_sync(0xffffffffu, dlo, o);
                dhi += __shfl_xor_sync(0xffffffffu, dhi, o);
            }
            if ((lane & 3) == 0) {
                int row0 = bm0 + wm + mt * 16 + (lane >> 2);
                if (row0 < M) {
                    atomicAdd(&out_als[row0], slo);
                    atomicAdd(&out_ald[row0], dlo);
                }
                if (row0 + 8 < M) {
                    atomicAdd(&out_als[row0 + 8], shi);
                    atomicAdd(&out_ald[row0 + 8], dhi);
                }
            }
        }
    }
}

#define G1_SMEM ((2 * 128 * AS_LD + 2 * 32 * (256 + 8)) * 4)
#define G2_SMEM ((2 * 128 * AS_LD + 2 * 32 * (128 + 8)) * 4)

// ---------------- layer-1: warp-per-node softmax+aggregate+bias+LN+ELU -----------
// h1 gathered as half2 (uint4 = 8 channels per lane).
__global__ void __launch_bounds__(256)
gat1_warp_kernel(const float* __restrict__ b, const float* __restrict__ g,
                 const float* __restrict__ beta, int Nn) {
    __shared__ float sh_rae[48];
    const int t = threadIdx.x;
    if (t < 48) sh_rae[t] = g_rae[t];
    __syncthreads();

    const int d = blockIdx.x * 8 + (t >> 5);
    if (d >= Nn) return;
    const int lane = t & 31;
    const int hl = lane >> 2;

    const int beg = g_off[d], end = g_off[d + 1];
    const float aldl = g_ald1[d * 8 + hl];

    float acc[8] = {0.f, 0.f, 0.f, 0.f, 0.f, 0.f, 0.f, 0.f};
    float den = 0.f, sumrae = 0.f;

    #pragma unroll 2
    for (int e = beg; e < end; ++e) {
        int p = g_csr_pack[e];
        int s = p & 0xFFFFF, r = p >> 20;
        float rv = sh_rae[r * 8 + hl];
        float a = g_als1[s * 8 + hl] + aldl + rv;
        a = a > 0.f ? a : 0.2f * a;
        float ex = __expf(a);
        den += ex;
        sumrae += rv;
        uint4 u = reinterpret_cast<const uint4*>(g_h1h + (size_t)s * 128)[lane];
        float2 f0 = __half22float2(*reinterpret_cast<__half2*>(&u.x));
        float2 f1 = __half22float2(*reinterpret_cast<__half2*>(&u.y));
        float2 f2 = __half22float2(*reinterpret_cast<__half2*>(&u.z));
        float2 f3 = __half22float2(*reinterpret_cast<__half2*>(&u.w));
        acc[0] += ex * f0.x; acc[1] += ex * f0.y;
        acc[2] += ex * f1.x; acc[3] += ex * f1.y;
        acc[4] += ex * f2.x; acc[5] += ex * f2.y;
        acc[6] += ex * f3.x; acc[7] += ex * f3.y;
    }

    float deg = (float)(end - beg);
    float asf = g_als1[d * 8 + hl] + aldl + sumrae / fmaxf(deg, 1.f);
    asf = asf > 0.f ? asf : 0.2f * asf;
    float exs = __expf(asf);
    den += exs;
    {
        uint4 u = reinterpret_cast<const uint4*>(g_h1h + (size_t)d * 128)[lane];
        float2 f0 = __half22float2(*reinterpret_cast<__half2*>(&u.x));
        float2 f1 = __half22float2(*reinterpret_cast<__half2*>(&u.y));
        float2 f2 = __half22float2(*reinterpret_cast<__half2*>(&u.z));
        float2 f3 = __half22float2(*reinterpret_cast<__half2*>(&u.w));
        acc[0] += exs * f0.x; acc[1] += exs * f0.y;
        acc[2] += exs * f1.x; acc[3] += exs * f1.y;
        acc[4] += exs * f2.x; acc[5] += exs * f2.y;
        acc[6] += exs * f3.x; acc[7] += exs * f3.y;
    }

    float inv = 1.f / (den + 1e-16f);
    const float4* bp = reinterpret_cast<const float4*>(b);
    float4 b0 = bp[lane * 2], b1 = bp[lane * 2 + 1];
    float v[8];
    v[0] = acc[0] * inv + b0.x; v[1] = acc[1] * inv + b0.y;
    v[2] = acc[2] * inv + b0.z; v[3] = acc[3] * inv + b0.w;
    v[4] = acc[4] * inv + b1.x; v[5] = acc[5] * inv + b1.y;
    v[6] = acc[6] * inv + b1.z; v[7] = acc[7] * inv + b1.w;

    float s1 = 0.f, s2 = 0.f;
    #pragma unroll
    for (int k = 0; k < 8; ++k) { s1 += v[k]; s2 += v[k] * v[k]; }
    #pragma unroll
    for (int o = 16; o; o >>= 1) {
        s1 += __shfl_xor_sync(0xffffffffu, s1, o);
        s2 += __shfl_xor_sync(0xffffffffu, s2, o);
    }
    float m = s1 * (1.f / 256.f);
    float var = s2 * (1.f / 256.f) - m * m;
    float rstd = rsqrtf(var + 1e-5f);

    const float4* gp = reinterpret_cast<const float4*>(g);
    const float4* betap = reinterpret_cast<const float4*>(beta);
    float4 g0 = gp[lane * 2], g1v = gp[lane * 2 + 1];
    float4 be0 = betap[lane * 2], be1 = betap[lane * 2 + 1];
    float gg[8] = {g0.x, g0.y, g0.z, g0.w, g1v.x, g1v.y, g1v.z, g1v.w};
    float bb[8] = {be0.x, be0.y, be0.z, be0.w, be1.x, be1.y, be1.z, be1.w};
    float y[8];
    #pragma unroll
    for (int k = 0; k < 8; ++k) {
        float yy = (v[k] - m) * rstd * gg[k] + bb[k];
        y[k] = yy > 0.f ? yy : expm1f(yy);
    }
    float4* op = reinterpret_cast<float4*>(g_out1 + (size_t)d * 256);
    op[lane * 2]     = make_float4(y[0], y[1], y[2], y[3]);
    op[lane * 2 + 1] = make_float4(y[4], y[5], y[6], y[7]);
}

// ---------------- layer-2: warp-per-node softmax+aggregate+bias+LN ---------------
// h2 gathered as half2 (uint2 = 4 channels per lane).
__global__ void __launch_bounds__(256)
gat2_warp_kernel(const float* __restrict__ b, const float* __restrict__ g,
                 const float* __restrict__ beta, float* __restrict__ out, int Nn) {
    const int t = threadIdx.x;
    const int d = blockIdx.x * 8 + (t >> 5);
    if (d >= Nn) return;
    const int lane = t & 31;

    const int beg = g_off[d], end = g_off[d + 1];
    const float ald = g_ald2[d];

    float acc[4] = {0.f, 0.f, 0.f, 0.f};
    float den = 0.f;

    #pragma unroll 2
    for (int e = beg; e < end; ++e) {
        int s = g_csr_pack[e] & 0xFFFFF;
        float a = g_als2[s] + ald;
        a = a > 0.f ? a : 0.2f * a;
        float ex = __expf(a);
        den += ex;
        uint2 u = reinterpret_cast<const uint2*>(g_h2h + (size_t)s * 64)[lane];
        float2 f0 = __half22float2(*reinterpret_cast<__half2*>(&u.x));
        float2 f1 = __half22float2(*reinterpret_cast<__half2*>(&u.y));
        acc[0] += ex * f0.x; acc[1] += ex * f0.y;
        acc[2] += ex * f1.x; acc[3] += ex * f1.y;
    }

    float asf = g_als2[d] + ald;
    asf = asf > 0.f ? asf : 0.2f * asf;
    float exs = __expf(asf);
    den += exs;
    {
        uint2 u = reinterpret_cast<const uint2*>(g_h2h + (size_t)d * 64)[lane];
        float2 f0 = __half22float2(*reinterpret_cast<__half2*>(&u.x));
        float2 f1 = __half22float2(*reinterpret_cast<__half2*>(&u.y));
        acc[0] += exs * f0.x; acc[1] += exs * f0.y;
        acc[2] += exs * f1.x; acc[3] += exs * f1.y;
    }

    float inv = 1.f / (den + 1e-16f);
    float4 bv = reinterpret_cast<const float4*>(b)[lane];
    float v[4];
    v[0] = acc[0] * inv + bv.x; v[1] = acc[1] * inv + bv.y;
    v[2] = acc[2] * inv + bv.z; v[3] = acc[3] * inv + bv.w;

    float s1 = 0.f, s2 = 0.f;
    #pragma unroll
    for (int k = 0; k < 4; ++k) { s1 += v[k]; s2 += v[k] * v[k]; }
    #pragma unroll
    for (int o = 16; o; o >>= 1) {
        s1 += __shfl_xor_sync(0xffffffffu, s1, o);
        s2 += __shfl_xor_sync(0xffffffffu, s2, o);
    }
    float m = s1 * (1.f / 128.f);
    float var = s2 * (1.f / 128.f) - m * m;
    float rstd = rsqrtf(var + 1e-5f);

    float4 gv = reinterpret_cast<const float4*>(g)[lane];
    float4 bev = reinterpret_cast<const float4*>(beta)[lane];
    float4 o4;
    o4.x = (v[0] - m) * rstd * gv.x + bev.x;
    o4.y = (v[1] - m) * rstd * gv.y + bev.y;
    o4.z = (v[2] - m) * rstd * gv.z + bev.z;
    o4.w = (v[3] - m) * rstd * gv.w + bev.w;
    reinterpret_cast<float4*>(out + (size_t)d * 128)[lane] = o4;
}

// ---------------- launch -----------------------------------------------------------
extern "C" void kernel_launch(void* const* d_in, const int* in_sizes, int n_in,
                              void* d_out, int out_size) {
    const float* x       = (const float*)d_in[0];
    const int*   ei      = (const int*)d_in[1];
    const int*   etype   = (const int*)d_in[2];
    const float* rel_emb = (const float*)d_in[3];
    const float* W1      = (const float*)d_in[4];
    const float* as1     = (const float*)d_in[5];
    const float* ad1     = (const float*)d_in[6];
    const float* We1     = (const float*)d_in[7];
    const float* ae1     = (const float*)d_in[8];
    const float* b1      = (const float*)d_in[9];
    const float* g1      = (const float*)d_in[10];
    const float* beta1   = (const float*)d_in[11];
    const float* W2      = (const float*)d_in[12];
    const float* as2     = (const float*)d_in[13];
    const float* ad2     = (const float*)d_in[14];
    const float* b2      = (const float*)d_in[15];
    const float* g2      = (const float*)d_in[16];
    const float* beta2   = (const float*)d_in[17];
    float* out = (float*)d_out;

    const int E = in_sizes[2];
    const int Nn = in_sizes[0] / 768;
    const int* src0 = ei;
    const int* dst0 = ei + E;
    const int nb = (Nn + 1023) / 1024;
    const int nm = (Nn + 127) / 128;

    float *pout1, *pals1, *pald1, *pals2, *pald2;
    unsigned int *ph1h, *ph2h;
    cudaGetSymbolAddress((void**)&ph1h, g_h1h);
    cudaGetSymbolAddress((void**)&ph2h, g_h2h);
    cudaGetSymbolAddress((void**)&pout1, g_out1);
    cudaGetSymbolAddress((void**)&pals1, g_als1);
    cudaGetSymbolAddress((void**)&pald1, g_ald1);
    cudaGetSymbolAddress((void**)&pals2, g_als2);
    cudaGetSymbolAddress((void**)&pald2, g_ald2);

    static cudaStream_t s_side = nullptr;
    static cudaEvent_t ev_fork = nullptr, ev_join = nullptr;
    if (!s_side) {
        cudaFuncSetAttribute(gemm_tf32_kernel<256, 1>,
                             cudaFuncAttributeMaxDynamicSharedMemorySize, G1_SMEM);
        cudaFuncSetAttribute(gemm_tf32_kernel<128, 2>,
                             cudaFuncAttributeMaxDynamicSharedMemorySize, G2_SMEM);
        cudaStreamCreateWithFlags(&s_side, cudaStreamNonBlocking);
        cudaEventCreateWithFlags(&ev_fork, cudaEventDisableTiming);
        cudaEventCreateWithFlags(&ev_join, cudaEventDisableTiming);
    }

    // ---- fork: CSR build + prep on side stream, GEMM1 on main stream ----
    cudaEventRecord(ev_fork, 0);
    cudaStreamWaitEvent(s_side, ev_fork, 0);

    init_kernel<<<(Nn + 255) / 256, 256, 0, s_side>>>(Nn);
    prep_kernel<<<1, 512, 0, s_side>>>(We1, ae1, rel_emb);
    hist_kernel<<<(E + 255) / 256, 256, 0, s_side>>>(dst0, E);
    scan_part_kernel<<<nb, 1024, 0, s_side>>>(Nn);
    scan_tops_kernel<<<1, 64, 0, s_side>>>(nb);
    scan_add_kernel<<<(Nn + 255) / 256, 256, 0, s_side>>>(Nn, E);
    scatter_kernel<<<(E + 255) / 256, 256, 0, s_side>>>(src0, dst0, etype, E);
    cudaEventRecord(ev_join, s_side);

    // GEMM1: h1 = x @ W1  [Nn,768]x[768,256] -> half2, fused attn1
    {
        dim3 grid(1, nm);
        gemm_tf32_kernel<256, 1><<<grid, 256, G1_SMEM>>>(
            x, W1, ph1h, Nn, 256, 768, as1, ad1, pals1, pald1);
    }

    // ---- join ----
    cudaStreamWaitEvent(0, ev_join, 0);

    gat1_warp_kernel<<<(Nn + 7) / 8, 256>>>(b1, g1, beta1, Nn);

    // GEMM2: h2 = out1 @ W2  [Nn,256]x[256,128] -> half2, fused attn2
    {
        dim3 grid(1, nm);
        gemm_tf32_kernel<128, 2><<<grid, 256, G2_SMEM>>>(
            pout1, W2, ph2h, Nn, 128, 256, as2, ad2, pals2, pald2);
    }
    gat2_warp_kernel<<<(Nn + 7) / 8, 256>>>(b2, g2, beta2, out, Nn);
}

// round 16
// speedup vs baseline: 1.1327x; 1.0877x over previous
#include <cuda_runtime.h>
#include <cuda_fp16.h>
#include <math.h>
#include <stdint.h>

#define NMAX 50000
#define EMAX 800000

// ---------------- scratch (static device globals) ----------------------------
__device__ unsigned int g_xh[NMAX * 384];    // x as fp16, row-major (768 halves)
__device__ unsigned int g_w1p[384 * 256];    // W1 packed k-pairs: [K/2][N]
__device__ unsigned int g_w2p[128 * 128];    // W2 packed k-pairs
__device__ unsigned int g_h1h[NMAX * 128];   // h1 fp16 (256 ch)
__device__ unsigned int g_out1h[NMAX * 128]; // out1 fp16 (256 ch) = GEMM2 A
__device__ unsigned int g_h2h[NMAX * 64];    // h2 fp16 (128 ch)
__device__ float g_als1[NMAX * 8];
__device__ float g_ald1[NMAX * 8];
__device__ float g_als2[NMAX];
__device__ float g_ald2[NMAX];
__device__ float g_rae[48];
__device__ int   g_off[NMAX + 1];
__device__ int   g_cur[NMAX];
__device__ int   g_bsum[64];
__device__ int   g_csr_pack[EMAX];           // src | (type << 20)

__device__ __forceinline__ unsigned int pack_h2(float a, float b) {
    __half2 h = __floats2half2_rn(a, b);
    return *reinterpret_cast<unsigned int*>(&h);
}
__device__ __forceinline__ uint32_t smem_u32(const void* p) {
    return (uint32_t)__cvta_generic_to_shared(p);
}

// ---------------- init ------------------------------------------------------------
__global__ void init_kernel(int Nn) {
    int i = blockIdx.x * blockDim.x + threadIdx.x;
    if (i < Nn) {
        g_cur[i] = 0;
        g_als2[i] = 0.f;
        g_ald2[i] = 0.f;
    }
}

// ---------------- x -> fp16 ---------------------------------------------------------
__global__ void convert_x_kernel(const float4* __restrict__ x4, int n4) {
    int i = blockIdx.x * blockDim.x + threadIdx.x;
    if (i < n4) {
        float4 v = x4[i];
        uint2 o;
        o.x = pack_h2(v.x, v.y);
        o.y = pack_h2(v.z, v.w);
        reinterpret_cast<uint2*>(g_xh)[i] = o;
    }
}

// ---------------- W -> fp16 packed k-pairs ------------------------------------------
__global__ void pack_w_kernel(const float* __restrict__ W,
                              unsigned int* __restrict__ Wp, int K, int N) {
    int i = blockIdx.x * blockDim.x + threadIdx.x;
    if (i >= (K / 2) * N) return;
    int k2 = i / N, n = i - k2 * N;
    Wp[i] = pack_h2(W[(2 * k2) * N + n], W[(2 * k2 + 1) * N + n]);
}

// ---------------- collapse edge-feature attention -----------------------------------
__global__ void prep_kernel(const float* __restrict__ We1,
                            const float* __restrict__ atte,
                            const float* __restrict__ rel_emb) {
    __shared__ float sve[64 * 8];
    int t = threadIdx.x;                 // 512 threads
    int d = t >> 3, h = t & 7;
    float s = 0.f;
    #pragma unroll
    for (int c = 0; c < 32; ++c)
        s += We1[d * 256 + h * 32 + c] * atte[h * 32 + c];
    sve[t] = s;
    __syncthreads();
    if (t < 48) {
        int r = t >> 3, hh = t & 7;
        float acc = 0.f;
        #pragma unroll
        for (int dd = 0; dd < 64; ++dd)
            acc += rel_emb[r * 64 + dd] * sve[dd * 8 + hh];
        g_rae[t] = acc;
    }
}

// ---------------- CSR build ----------------------------------------------------------
__global__ void hist_kernel(const int* __restrict__ dst0, int E) {
    int e = blockIdx.x * blockDim.x + threadIdx.x;
    if (e < E) atomicAdd(&g_cur[dst0[e]], 1);
}

__global__ void scan_part_kernel(int Nn) {
    __shared__ int sh[1024];
    int t = threadIdx.x;
    int i = blockIdx.x * 1024 + t;
    int v = (i < Nn) ? g_cur[i] : 0;
    sh[t] = v;
    __syncthreads();
    #pragma unroll
    for (int o = 1; o < 1024; o <<= 1) {
        int add = (t >= o) ? sh[t - o] : 0;
        __syncthreads();
        sh[t] += add;
        __syncthreads();
    }
    if (i < Nn) g_off[i] = sh[t] - v;
    if (t == 1023) g_bsum[blockIdx.x] = sh[1023];
}

__global__ void scan_tops_kernel(int nb) {
    __shared__ int sh[64];
    int t = threadIdx.x;
    int v = (t < nb) ? g_bsum[t] : 0;
    sh[t] = v;
    __syncthreads();
    #pragma unroll
    for (int o = 1; o < 64; o <<= 1) {
        int add = (t >= o) ? sh[t - o] : 0;
        __syncthreads();
        sh[t] += add;
        __syncthreads();
    }
    g_bsum[t] = sh[t] - v;
}

__global__ void scan_add_kernel(int Nn, int E) {
    int i = blockIdx.x * blockDim.x + threadIdx.x;
    if (i < Nn) {
        int o = g_off[i] + g_bsum[i >> 10];
        g_off[i] = o;
        g_cur[i] = o;
    }
    if (i == 0) g_off[Nn] = E;
}

__global__ void scatter_kernel(const int* __restrict__ src0,
                               const int* __restrict__ dst0,
                               const int* __restrict__ etype, int E) {
    int e = blockIdx.x * blockDim.x + threadIdx.x;
    if (e >= E) return;
    int d = dst0[e];
    int pos = atomicAdd(&g_cur[d], 1);
    g_csr_pack[pos] = src0[e] | (etype[e] << 20);
}

// ---------------- FP16 tensor-core GEMM (m16n8k16), half2 out + fused epilogues -----
__device__ __forceinline__ void mma_fp16(float* c, const uint32_t* a, const uint32_t* b) {
    asm volatile(
        "mma.sync.aligned.m16n8k16.row.col.f32.f16.f16.f32 "
        "{%0,%1,%2,%3}, {%4,%5,%6,%7}, {%8,%9}, {%0,%1,%2,%3};"
        : "+f"(c[0]), "+f"(c[1]), "+f"(c[2]), "+f"(c[3])
        : "r"(a[0]), "r"(a[1]), "r"(a[2]), "r"(a[3]), "r"(b[0]), "r"(b[1]));
}

#define AH_LD 20   // uint words per A smem row (16 data + 4 pad); r*20 mod 32 distinct
// A: fp16 row-major [M][K] (halves). Bp: [K/2][N] uints (k-pair packed).
// K-tile = 32 (16 words). 8 warps 2x4, warp tile 64 x (BN/4).
// FUSE_MODE 1: layer-1 per-head logits; 2: layer-2 logits via atomicAdd.
template <int BN, int FUSE_MODE>
__global__ void __launch_bounds__(256, (BN == 128) ? 2 : 1)
gemm_fp16_kernel(const unsigned short* __restrict__ Ah,
                 const unsigned int* __restrict__ Bp,
                 unsigned int* __restrict__ Ch, int M, int N, int K,
                 const float* __restrict__ attn_s, const float* __restrict__ attn_d,
                 float* __restrict__ out_als, float* __restrict__ out_ald) {
    constexpr int BSH_LD = BN + 8;
    constexpr int WN = BN / 4;
    constexpr int NT = WN / 8;
    constexpr int NHEAD = WN / 32;
    constexpr int A_STG = 128 * AH_LD;       // words per stage
    constexpr int B_STG = 16 * BSH_LD;

    extern __shared__ unsigned int dynsm[];
    unsigned int* AsBase = dynsm;
    unsigned int* BsBase = dynsm + 2 * A_STG;

    const int tid = threadIdx.x;
    const int lane = tid & 31, wid = tid >> 5;
    const int wm = (wid >> 2) * 64;
    const int wn = (wid & 3) * WN;
    const int bn0 = blockIdx.x * BN;
    const int bm0 = blockIdx.y * 128;

    float acc[4][NT][4];
    #pragma unroll
    for (int i = 0; i < 4; ++i)
        #pragma unroll
        for (int j = 0; j < NT; ++j)
            #pragma unroll
            for (int k = 0; k < 4; ++k) acc[i][j][k] = 0.f;

    const int nk = K >> 5;

    auto load_stage = [&](int kt, int buf) {
        const int k0 = kt * 32;
        unsigned int* As = AsBase + buf * A_STG;
        unsigned int* Bs = BsBase + buf * B_STG;
        // A: 128 rows x 4 chunks of 16B (8 halves)
        #pragma unroll
        for (int i = 0; i < 2; ++i) {
            int u = tid + i * 256;
            int row = u >> 2, ch = u & 3;
            int grow = bm0 + row;
            int ok = (grow < M);
            const unsigned short* src = Ah + (size_t)(ok ? grow : 0) * K + k0 + ch * 8;
            uint32_t dst = smem_u32(&As[row * AH_LD + ch * 4]);
            int nb = ok ? 16 : 0;
            asm volatile("cp.async.ca.shared.global [%0], [%1], 16, %2;"
                         :: "r"(dst), "l"(src), "r"(nb));
        }
        // B: 16 pair-rows x BN words; 16B chunks (4 words)
        constexpr int BU = BN / 64;          // units per thread
        #pragma unroll
        for (int i = 0; i < BU; ++i) {
            int u = tid + i * 256;
            int row = u / (BN / 4);
            int col4 = (u % (BN / 4)) * 4;
            const unsigned int* src = Bp + (size_t)(k0 / 2 + row) * N + bn0 + col4;
            uint32_t dst = smem_u32(&Bs[row * BSH_LD + col4]);
            asm volatile("cp.async.ca.shared.global [%0], [%1], 16;"
                         :: "r"(dst), "l"(src));
        }
        asm volatile("cp.async.commit_group;");
    };

    load_stage(0, 0);

    for (int kt = 0; kt < nk; ++kt) {
        const int buf = kt & 1;
        if (kt + 1 < nk) load_stage(kt + 1, buf ^ 1);
        else asm volatile("cp.async.commit_group;");
        asm volatile("cp.async.wait_group 1;");
        __syncthreads();

        const unsigned int* as = AsBase + buf * A_STG;
        const unsigned int* bs = BsBase + buf * B_STG;
        #pragma unroll
        for (int kk = 0; kk < 2; ++kk) {       // 2 x k16
            const int kb2 = kk * 8;            // pair-word offset
            uint32_t afrag[4][4], bfrag[NT][2];
            #pragma unroll
            for (int mt = 0; mt < 4; ++mt) {
                int r0 = wm + mt * 16 + (lane >> 2);
                int c0 = kb2 + (lane & 3);
                afrag[mt][0] = as[r0 * AH_LD + c0];
                afrag[mt][1] = as[(r0 + 8) * AH_LD + c0];
                afrag[mt][2] = as[r0 * AH_LD + c0 + 4];
                afrag[mt][3] = as[(r0 + 8) * AH_LD + c0 + 4];
            }
            #pragma unroll
            for (int nt = 0; nt < NT; ++nt) {
                int n0 = wn + nt * 8 + (lane >> 2);
                int kr = kb2 + (lane & 3);
                bfrag[nt][0] = bs[kr * BSH_LD + n0];
                bfrag[nt][1] = bs[(kr + 4) * BSH_LD + n0];
            }
            #pragma unroll
            for (int mt = 0; mt < 4; ++mt)
                #pragma unroll
                for (int nt = 0; nt < NT; ++nt)
                    mma_fp16(acc[mt][nt], afrag[mt], bfrag[nt]);
        }
        __syncthreads();
    }

    // ---- store C as half2 pairs ----
    const int NH = N / 2;
    #pragma unroll
    for (int mt = 0; mt < 4; ++mt) {
        int row0 = bm0 + wm + mt * 16 + (lane >> 2);
        #pragma unroll
        for (int nt = 0; nt < NT; ++nt) {
            int cp = (bn0 + wn + nt * 8 + (lane & 3) * 2) >> 1;
            if (row0 < M)
                Ch[(size_t)row0 * NH + cp] = pack_h2(acc[mt][nt][0], acc[mt][nt][1]);
            if (row0 + 8 < M)
                Ch[(size_t)(row0 + 8) * NH + cp] = pack_h2(acc[mt][nt][2], acc[mt][nt][3]);
        }
    }

    // ---- fused attention-logit epilogues (fp32 accumulators) ----
    if constexpr (FUSE_MODE == 1) {
        float asv[NT][2], adv[NT][2];
        #pragma unroll
        for (int nt = 0; nt < NT; ++nt) {
            int col = bn0 + wn + nt * 8 + (lane & 3) * 2;
            asv[nt][0] = attn_s[col];     asv[nt][1] = attn_s[col + 1];
            adv[nt][0] = attn_d[col];     adv[nt][1] = attn_d[col + 1];
        }
        #pragma unroll
        for (int mt = 0; mt < 4; ++mt) {
            #pragma unroll
            for (int hh = 0; hh < NHEAD; ++hh) {
                float slo = 0.f, shi = 0.f, dlo = 0.f, dhi = 0.f;
                #pragma unroll
                for (int q = 0; q < 4; ++q) {
                    int nt = hh * 4 + q;
                    slo += acc[mt][nt][0] * asv[nt][0] + acc[mt][nt][1] * asv[nt][1];
                    shi += acc[mt][nt][2] * asv[nt][0] + acc[mt][nt][3] * asv[nt][1];
                    dlo += acc[mt][nt][0] * adv[nt][0] + acc[mt][nt][1] * adv[nt][1];
                    dhi += acc[mt][nt][2] * adv[nt][0] + acc[mt][nt][3] * adv[nt][1];
                }
                #pragma unroll
                for (int o = 1; o <= 2; o <<= 1) {
                    slo += __shfl_xor_sync(0xffffffffu, slo, o);
                    shi += __shfl_xor_sync(0xffffffffu, shi, o);
                    dlo += __shfl_xor_sync(0xffffffffu, dlo, o);
                    dhi += __shfl_xor_sync(0xffffffffu, dhi, o);
                }
                if ((lane & 3) == 0) {
                    int head = (bn0 + wn) / 32 + hh;
                    int row0 = bm0 + wm + mt * 16 + (lane >> 2);
                    if (row0 < M) {
                        out_als[row0 * 8 + head] = slo;
                        out_ald[row0 * 8 + head] = dlo;
                    }
                    if (row0 + 8 < M) {
                        out_als[(row0 + 8) * 8 + head] = shi;
                        out_ald[(row0 + 8) * 8 + head] = dhi;
                    }
                }
            }
        }
    }
    if constexpr (FUSE_MODE == 2) {
        float asv[NT][2], adv[NT][2];
        #pragma unroll
        for (int nt = 0; nt < NT; ++nt) {
            int col = bn0 + wn + nt * 8 + (lane & 3) * 2;
            asv[nt][0] = attn_s[col];     asv[nt][1] = attn_s[col + 1];
            adv[nt][0] = attn_d[col];     adv[nt][1] = attn_d[col + 1];
        }
        #pragma unroll
        for (int mt = 0; mt < 4; ++mt) {
            float slo = 0.f, shi = 0.f, dlo = 0.f, dhi = 0.f;
            #pragma unroll
            for (int nt = 0; nt < NT; ++nt) {
                slo += acc[mt][nt][0] * asv[nt][0] + acc[mt][nt][1] * asv[nt][1];
                shi += acc[mt][nt][2] * asv[nt][0] + acc[mt][nt][3] * asv[nt][1];
                dlo += acc[mt][nt][0] * adv[nt][0] + acc[mt][nt][1] * adv[nt][1];
                dhi += acc[mt][nt][2] * adv[nt][0] + acc[mt][nt][3] * adv[nt][1];
            }
            #pragma unroll
            for (int o = 1; o <= 2; o <<= 1) {
                slo += __shfl_xor_sync(0xffffffffu, slo, o);
                shi += __shfl_xor_sync(0xffffffffu, shi, o);
                dlo += __shfl_xor_sync(0xffffffffu, dlo, o);
                dhi += __shfl_xor_sync(0xffffffffu, dhi, o);
            }
            if ((lane & 3) == 0) {
                int row0 = bm0 + wm + mt * 16 + (lane >> 2);
                if (row0 < M) {
                    atomicAdd(&out_als[row0], slo);
                    atomicAdd(&out_ald[row0], dlo);
                }
                if (row0 + 8 < M) {
                    atomicAdd(&out_als[row0 + 8], shi);
                    atomicAdd(&out_ald[row0 + 8], dhi);
                }
            }
        }
    }
}

#define G1_SMEM ((2 * 128 * AH_LD + 2 * 16 * (256 + 8)) * 4)
#define G2_SMEM ((2 * 128 * AH_LD + 2 * 16 * (128 + 8)) * 4)

// ---------------- layer-1: warp-per-node softmax+aggregate+bias+LN+ELU -------------
__global__ void __launch_bounds__(256)
gat1_warp_kernel(const float* __restrict__ b, const float* __restrict__ g,
                 const float* __restrict__ beta, int Nn) {
    __shared__ float sh_rae[48];
    const int t = threadIdx.x;
    if (t < 48) sh_rae[t] = g_rae[t];
    __syncthreads();

    const int d = blockIdx.x * 8 + (t >> 5);
    if (d >= Nn) return;
    const int lane = t & 31;
    const int hl = lane >> 2;

    const int beg = g_off[d], end = g_off[d + 1];
    const float aldl = g_ald1[d * 8 + hl];

    float acc[8] = {0.f, 0.f, 0.f, 0.f, 0.f, 0.f, 0.f, 0.f};
    float den = 0.f, sumrae = 0.f;

    #pragma unroll 2
    for (int e = beg; e < end; ++e) {
        int p = g_csr_pack[e];
        int s = p & 0xFFFFF, r = p >> 20;
        float rv = sh_rae[r * 8 + hl];
        float a = g_als1[s * 8 + hl] + aldl + rv;
        a = a > 0.f ? a : 0.2f * a;
        float ex = __expf(a);
        den += ex;
        sumrae += rv;
        uint4 u = reinterpret_cast<const uint4*>(g_h1h + (size_t)s * 128)[lane];
        float2 f0 = __half22float2(*reinterpret_cast<__half2*>(&u.x));
        float2 f1 = __half22float2(*reinterpret_cast<__half2*>(&u.y));
        float2 f2 = __half22float2(*reinterpret_cast<__half2*>(&u.z));
        float2 f3 = __half22float2(*reinterpret_cast<__half2*>(&u.w));
        acc[0] += ex * f0.x; acc[1] += ex * f0.y;
        acc[2] += ex * f1.x; acc[3] += ex * f1.y;
        acc[4] += ex * f2.x; acc[5] += ex * f2.y;
        acc[6] += ex * f3.x; acc[7] += ex * f3.y;
    }

    float deg = (float)(end - beg);
    float asf = g_als1[d * 8 + hl] + aldl + sumrae / fmaxf(deg, 1.f);
    asf = asf > 0.f ? asf : 0.2f * asf;
    float exs = __expf(asf);
    den += exs;
    {
        uint4 u = reinterpret_cast<const uint4*>(g_h1h + (size_t)d * 128)[lane];
        float2 f0 = __half22float2(*reinterpret_cast<__half2*>(&u.x));
        float2 f1 = __half22float2(*reinterpret_cast<__half2*>(&u.y));
        float2 f2 = __half22float2(*reinterpret_cast<__half2*>(&u.z));
        float2 f3 = __half22float2(*reinterpret_cast<__half2*>(&u.w));
        acc[0] += exs * f0.x; acc[1] += exs * f0.y;
        acc[2] += exs * f1.x; acc[3] += exs * f1.y;
        acc[4] += exs * f2.x; acc[5] += exs * f2.y;
        acc[6] += exs * f3.x; acc[7] += exs * f3.y;
    }

    float inv = 1.f / (den + 1e-16f);
    const float4* bp = reinterpret_cast<const float4*>(b);
    float4 b0 = bp[lane * 2], b1 = bp[lane * 2 + 1];
    float v[8];
    v[0] = acc[0] * inv + b0.x; v[1] = acc[1] * inv + b0.y;
    v[2] = acc[2] * inv + b0.z; v[3] = acc[3] * inv + b0.w;
    v[4] = acc[4] * inv + b1.x; v[5] = acc[5] * inv + b1.y;
    v[6] = acc[6] * inv + b1.z; v[7] = acc[7] * inv + b1.w;

    float s1 = 0.f, s2 = 0.f;
    #pragma unroll
    for (int k = 0; k < 8; ++k) { s1 += v[k]; s2 += v[k] * v[k]; }
    #pragma unroll
    for (int o = 16; o; o >>= 1) {
        s1 += __shfl_xor_sync(0xffffffffu, s1, o);
        s2 += __shfl_xor_sync(0xffffffffu, s2, o);
    }
    float m = s1 * (1.f / 256.f);
    float var = s2 * (1.f / 256.f) - m * m;
    float rstd = rsqrtf(var + 1e-5f);

    const float4* gp = reinterpret_cast<const float4*>(g);
    const float4* betap = reinterpret_cast<const float4*>(beta);
    float4 g0 = gp[lane * 2], g1v = gp[lane * 2 + 1];
    float4 be0 = betap[lane * 2], be1 = betap[lane * 2 + 1];
    float gg[8] = {g0.x, g0.y, g0.z, g0.w, g1v.x, g1v.y, g1v.z, g1v.w};
    float bb[8] = {be0.x, be0.y, be0.z, be0.w, be1.x, be1.y, be1.z, be1.w};
    float y[8];
    #pragma unroll
    for (int k = 0; k < 8; ++k) {
        float yy = (v[k] - m) * rstd * gg[k] + bb[k];
        y[k] = yy > 0.f ? yy : expm1f(yy);
    }
    uint4 o4;
    o4.x = pack_h2(y[0], y[1]);
    o4.y = pack_h2(y[2], y[3]);
    o4.z = pack_h2(y[4], y[5]);
    o4.w = pack_h2(y[6], y[7]);
    reinterpret_cast<uint4*>(g_out1h + (size_t)d * 128)[lane] = o4;
}

// ---------------- layer-2: warp-per-node softmax+aggregate+bias+LN -----------------
__global__ void __launch_bounds__(256)
gat2_warp_kernel(const float* __restrict__ b, const float* __restrict__ g,
                 const float* __restrict__ beta, float* __restrict__ out, int Nn) {
    const int t = threadIdx.x;
    const int d = blockIdx.x * 8 + (t >> 5);
    if (d >= Nn) return;
    const int lane = t & 31;

    const int beg = g_off[d], end = g_off[d + 1];
    const float ald = g_ald2[d];

    float acc[4] = {0.f, 0.f, 0.f, 0.f};
    float den = 0.f;

    #pragma unroll 2
    for (int e = beg; e < end; ++e) {
        int s = g_csr_pack[e] & 0xFFFFF;
        float a = g_als2[s] + ald;
        a = a > 0.f ? a : 0.2f * a;
        float ex = __expf(a);
        den += ex;
        uint2 u = reinterpret_cast<const uint2*>(g_h2h + (size_t)s * 64)[lane];
        float2 f0 = __half22float2(*reinterpret_cast<__half2*>(&u.x));
        float2 f1 = __half22float2(*reinterpret_cast<__half2*>(&u.y));
        acc[0] += ex * f0.x; acc[1] += ex * f0.y;
        acc[2] += ex * f1.x; acc[3] += ex * f1.y;
    }

    float asf = g_als2[d] + ald;
    asf = asf > 0.f ? asf : 0.2f * asf;
    float exs = __expf(asf);
    den += exs;
    {
        uint2 u = reinterpret_cast<const uint2*>(g_h2h + (size_t)d * 64)[lane];
        float2 f0 = __half22float2(*reinterpret_cast<__half2*>(&u.x));
        float2 f1 = __half22float2(*reinterpret_cast<__half2*>(&u.y));
        acc[0] += exs * f0.x; acc[1] += exs * f0.y;
        acc[2] += exs * f1.x; acc[3] += exs * f1.y;
    }

    float inv = 1.f / (den + 1e-16f);
    float4 bv = reinterpret_cast<const float4*>(b)[lane];
    float v[4];
    v[0] = acc[0] * inv + bv.x; v[1] = acc[1] * inv + bv.y;
    v[2] = acc[2] * inv + bv.z; v[3] = acc[3] * inv + bv.w;

    float s1 = 0.f, s2 = 0.f;
    #pragma unroll
    for (int k = 0; k < 4; ++k) { s1 += v[k]; s2 += v[k] * v[k]; }
    #pragma unroll
    for (int o = 16; o; o >>= 1) {
        s1 += __shfl_xor_sync(0xffffffffu, s1, o);
        s2 += __shfl_xor_sync(0xffffffffu, s2, o);
    }
    float m = s1 * (1.f / 128.f);
    float var = s2 * (1.f / 128.f) - m * m;
    float rstd = rsqrtf(var + 1e-5f);

    float4 gv = reinterpret_cast<const float4*>(g)[lane];
    float4 bev = reinterpret_cast<const float4*>(beta)[lane];
    float4 o4;
    o4.x = (v[0] - m) * rstd * gv.x + bev.x;
    o4.y = (v[1] - m) * rstd * gv.y + bev.y;
    o4.z = (v[2] - m) * rstd * gv.z + bev.z;
    o4.w = (v[3] - m) * rstd * gv.w + bev.w;
    reinterpret_cast<float4*>(out + (size_t)d * 128)[lane] = o4;
}

// ---------------- launch -------------------------------------------------------------
extern "C" void kernel_launch(void* const* d_in, const int* in_sizes, int n_in,
                              void* d_out, int out_size) {
    const float* x       = (const float*)d_in[0];
    const int*   ei      = (const int*)d_in[1];
    const int*   etype   = (const int*)d_in[2];
    const float* rel_emb = (const float*)d_in[3];
    const float* W1      = (const float*)d_in[4];
    const float* as1     = (const float*)d_in[5];
    const float* ad1     = (const float*)d_in[6];
    const float* We1     = (const float*)d_in[7];
    const float* ae1     = (const float*)d_in[8];
    const float* b1      = (const float*)d_in[9];
    const float* g1      = (const float*)d_in[10];
    const float* beta1   = (const float*)d_in[11];
    const float* W2      = (const float*)d_in[12];
    const float* as2     = (const float*)d_in[13];
    const float* ad2     = (const float*)d_in[14];
    const float* b2      = (const float*)d_in[15];
    const float* g2      = (const float*)d_in[16];
    const float* beta2   = (const float*)d_in[17];
    float* out = (float*)d_out;

    const int E = in_sizes[2];
    const int Nn = in_sizes[0] / 768;
    const int* src0 = ei;
    const int* dst0 = ei + E;
    const int nb = (Nn + 1023) / 1024;
    const int nm = (Nn + 127) / 128;

    float *pals1, *pald1, *pals2, *pald2;
    unsigned int *pxh, *pw1p, *pw2p, *ph1h, *pout1h, *ph2h;
    cudaGetSymbolAddress((void**)&pxh, g_xh);
    cudaGetSymbolAddress((void**)&pw1p, g_w1p);
    cudaGetSymbolAddress((void**)&pw2p, g_w2p);
    cudaGetSymbolAddress((void**)&ph1h, g_h1h);
    cudaGetSymbolAddress((void**)&pout1h, g_out1h);
    cudaGetSymbolAddress((void**)&ph2h, g_h2h);
    cudaGetSymbolAddress((void**)&pals1, g_als1);
    cudaGetSymbolAddress((void**)&pald1, g_ald1);
    cudaGetSymbolAddress((void**)&pals2, g_als2);
    cudaGetSymbolAddress((void**)&pald2, g_ald2);

    static cudaStream_t s_side = nullptr;
    static cudaEvent_t ev_fork = nullptr, ev_join = nullptr;
    if (!s_side) {
        cudaFuncSetAttribute(gemm_fp16_kernel<256, 1>,
                             cudaFuncAttributeMaxDynamicSharedMemorySize, G1_SMEM);
        cudaFuncSetAttribute(gemm_fp16_kernel<128, 2>,
                             cudaFuncAttributeMaxDynamicSharedMemorySize, G2_SMEM);
        cudaStreamCreateWithFlags(&s_side, cudaStreamNonBlocking);
        cudaEventCreateWithFlags(&ev_fork, cudaEventDisableTiming);
        cudaEventCreateWithFlags(&ev_join, cudaEventDisableTiming);
    }

    // ---- fork: CSR build + prep + W2 pack on side stream ----
    cudaEventRecord(ev_fork, 0);
    cudaStreamWaitEvent(s_side, ev_fork, 0);

    init_kernel<<<(Nn + 255) / 256, 256, 0, s_side>>>(Nn);
    prep_kernel<<<1, 512, 0, s_side>>>(We1, ae1, rel_emb);
    hist_kernel<<<(E + 255) / 256, 256, 0, s_side>>>(dst0, E);
    scan_part_kernel<<<nb, 1024, 0, s_side>>>(Nn);
    scan_tops_kernel<<<1, 64, 0, s_side>>>(nb);
    scan_add_kernel<<<(Nn + 255) / 256, 256, 0, s_side>>>(Nn, E);
    scatter_kernel<<<(E + 255) / 256, 256, 0, s_side>>>(src0, dst0, etype, E);
    pack_w_kernel<<<(128 * 128 + 255) / 256, 256, 0, s_side>>>(W2, pw2p, 256, 128);
    cudaEventRecord(ev_join, s_side);

    // ---- main: convert x + pack W1, then fp16 GEMM1 (fused attn1) ----
    convert_x_kernel<<<(Nn * 192 + 255) / 256, 256>>>(
        reinterpret_cast<const float4*>(x), Nn * 192);
    pack_w_kernel<<<(384 * 256 + 255) / 256, 256>>>(W1, pw1p, 768, 256);
    {
        dim3 grid(1, nm);
        gemm_fp16_kernel<256, 1><<<grid, 256, G1_SMEM>>>(
            (const unsigned short*)pxh, pw1p, ph1h, Nn, 256, 768,
            as1, ad1, pals1, pald1);
    }

    // ---- join ----
    cudaStreamWaitEvent(0, ev_join, 0);

    gat1_warp_kernel<<<(Nn + 7) / 8, 256>>>(b1, g1, beta1, Nn);

    // GEMM2: h2 = out1 @ W2 (fp16), fused attn2
    {
        dim3 grid(1, nm);
        gemm_fp16_kernel<128, 2><<<grid, 256, G2_SMEM>>>(
            (const unsigned short*)pout1h, pw2p, ph2h, Nn, 128, 256,
            as2, ad2, pals2, pald2);
    }
    gat2_warp_kernel<<<(Nn + 7) / 8, 256>>>(b2, g2, beta2, out, Nn);
}

// round 17
// speedup vs baseline: 1.2290x; 1.0849x over previous
#include <cuda_runtime.h>
#include <cuda_fp16.h>
#include <math.h>
#include <stdint.h>

#define NMAX 50000
#define EMAX 800000

// ---------------- scratch (static device globals) ----------------------------
__device__ unsigned int g_w1p[384 * 256];    // W1 packed k-pairs: [K/2][N]
__device__ unsigned int g_w2p[128 * 128];    // W2 packed k-pairs
__device__ unsigned int g_h1h[NMAX * 128];   // h1 fp16 (256 ch)
__device__ unsigned int g_out1h[NMAX * 128]; // out1 fp16 (256 ch) = GEMM2 A
__device__ unsigned int g_h2h[NMAX * 64];    // h2 fp16 (128 ch)
__device__ float g_als1[NMAX * 8];
__device__ float g_ald1[NMAX * 8];
__device__ float g_als2[NMAX];
__device__ float g_ald2[NMAX];
__device__ float g_rae[48];
__device__ int   g_off[NMAX + 1];
__device__ int   g_cur[NMAX];
__device__ int   g_bsum[64];
__device__ int   g_csr_pack[EMAX];           // src | (type << 20)

__device__ __forceinline__ unsigned int pack_h2(float a, float b) {
    __half2 h = __floats2half2_rn(a, b);
    return *reinterpret_cast<unsigned int*>(&h);
}
__device__ __forceinline__ uint32_t smem_u32(const void* p) {
    return (uint32_t)__cvta_generic_to_shared(p);
}

// ---------------- init ------------------------------------------------------------
__global__ void init_kernel(int Nn) {
    int i = blockIdx.x * blockDim.x + threadIdx.x;
    if (i < Nn) {
        g_cur[i] = 0;
        g_als2[i] = 0.f;
        g_ald2[i] = 0.f;
    }
}

// ---------------- W -> fp16 packed k-pairs ------------------------------------------
__global__ void pack_w_kernel(const float* __restrict__ W,
                              unsigned int* __restrict__ Wp, int K, int N) {
    int i = blockIdx.x * blockDim.x + threadIdx.x;
    if (i >= (K / 2) * N) return;
    int k2 = i / N, n = i - k2 * N;
    Wp[i] = pack_h2(W[(2 * k2) * N + n], W[(2 * k2 + 1) * N + n]);
}

// ---------------- collapse edge-feature attention -----------------------------------
__global__ void prep_kernel(const float* __restrict__ We1,
                            const float* __restrict__ atte,
                            const float* __restrict__ rel_emb) {
    __shared__ float sve[64 * 8];
    int t = threadIdx.x;                 // 512 threads
    int d = t >> 3, h = t & 7;
    float s = 0.f;
    #pragma unroll
    for (int c = 0; c < 32; ++c)
        s += We1[d * 256 + h * 32 + c] * atte[h * 32 + c];
    sve[t] = s;
    __syncthreads();
    if (t < 48) {
        int r = t >> 3, hh = t & 7;
        float acc = 0.f;
        #pragma unroll
        for (int dd = 0; dd < 64; ++dd)
            acc += rel_emb[r * 64 + dd] * sve[dd * 8 + hh];
        g_rae[t] = acc;
    }
}

// ---------------- CSR build ----------------------------------------------------------
__global__ void hist_kernel(const int* __restrict__ dst0, int E) {
    int e = blockIdx.x * blockDim.x + threadIdx.x;
    if (e < E) atomicAdd(&g_cur[dst0[e]], 1);
}

__global__ void scan_part_kernel(int Nn) {
    __shared__ int sh[1024];
    int t = threadIdx.x;
    int i = blockIdx.x * 1024 + t;
    int v = (i < Nn) ? g_cur[i] : 0;
    sh[t] = v;
    __syncthreads();
    #pragma unroll
    for (int o = 1; o < 1024; o <<= 1) {
        int add = (t >= o) ? sh[t - o] : 0;
        __syncthreads();
        sh[t] += add;
        __syncthreads();
    }
    if (i < Nn) g_off[i] = sh[t] - v;
    if (t == 1023) g_bsum[blockIdx.x] = sh[1023];
}

__global__ void scan_tops_kernel(int nb) {
    __shared__ int sh[64];
    int t = threadIdx.x;
    int v = (t < nb) ? g_bsum[t] : 0;
    sh[t] = v;
    __syncthreads();
    #pragma unroll
    for (int o = 1; o < 64; o <<= 1) {
        int add = (t >= o) ? sh[t - o] : 0;
        __syncthreads();
        sh[t] += add;
        __syncthreads();
    }
    g_bsum[t] = sh[t] - v;
}

__global__ void scan_add_kernel(int Nn, int E) {
    int i = blockIdx.x * blockDim.x + threadIdx.x;
    if (i < Nn) {
        int o = g_off[i] + g_bsum[i >> 10];
        g_off[i] = o;
        g_cur[i] = o;
    }
    if (i == 0) g_off[Nn] = E;
}

__global__ void scatter_kernel(const int* __restrict__ src0,
                               const int* __restrict__ dst0,
                               const int* __restrict__ etype, int E) {
    int e = blockIdx.x * blockDim.x + threadIdx.x;
    if (e >= E) return;
    int d = dst0[e];
    int pos = atomicAdd(&g_cur[d], 1);
    g_csr_pack[pos] = src0[e] | (etype[e] << 20);
}

// ---------------- FP16 tensor-core GEMM (m16n8k16), half2 out + fused epilogues -----
// AFP32: A staged in fp32, converted to fp16 pairs at fragment-load time.
__device__ __forceinline__ void mma_fp16(float* c, const uint32_t* a, const uint32_t* b) {
    asm volatile(
        "mma.sync.aligned.m16n8k16.row.col.f32.f16.f16.f32 "
        "{%0,%1,%2,%3}, {%4,%5,%6,%7}, {%8,%9}, {%0,%1,%2,%3};"
        : "+f"(c[0]), "+f"(c[1]), "+f"(c[2]), "+f"(c[3])
        : "r"(a[0]), "r"(a[1]), "r"(a[2]), "r"(a[3]), "r"(b[0]), "r"(b[1]));
}

#define AH_LD 20   // fp16 A: uint words/row (16 data + 4 pad)
#define AF_LD 18   // fp32 A: float2 units/row (16 data + 2 pad) = 36 floats
// FUSE_MODE 1: layer-1 per-head logits; 2: layer-2 logits via atomicAdd.
template <int BN, int FUSE_MODE, bool AFP32>
__global__ void __launch_bounds__(256, (BN == 128) ? 2 : 1)
gemm_fp16_kernel(const void* __restrict__ Aptr,
                 const unsigned int* __restrict__ Bp,
                 unsigned int* __restrict__ Ch, int M, int N, int K,
                 const float* __restrict__ attn_s, const float* __restrict__ attn_d,
                 float* __restrict__ out_als, float* __restrict__ out_ald) {
    constexpr int BSH_LD = BN + 8;
    constexpr int WN = BN / 4;
    constexpr int NT = WN / 8;
    constexpr int NHEAD = WN / 32;
    constexpr int A_STG = AFP32 ? (128 * AF_LD * 2) : (128 * AH_LD);  // in 4B words
    constexpr int B_STG = 16 * BSH_LD;

    extern __shared__ unsigned int dynsm[];
    unsigned int* AsBase = dynsm;
    unsigned int* BsBase = dynsm + 2 * A_STG;

    const int tid = threadIdx.x;
    const int lane = tid & 31, wid = tid >> 5;
    const int wm = (wid >> 2) * 64;
    const int wn = (wid & 3) * WN;
    const int bn0 = blockIdx.x * BN;
    const int bm0 = blockIdx.y * 128;

    float acc[4][NT][4];
    #pragma unroll
    for (int i = 0; i < 4; ++i)
        #pragma unroll
        for (int j = 0; j < NT; ++j)
            #pragma unroll
            for (int k = 0; k < 4; ++k) acc[i][j][k] = 0.f;

    const int nk = K >> 5;

    auto load_stage = [&](int kt, int buf) {
        const int k0 = kt * 32;
        unsigned int* As = AsBase + buf * A_STG;
        unsigned int* Bs = BsBase + buf * B_STG;
        if constexpr (AFP32) {
            // A: 128 rows x 32 floats; 8 chunks of 16B per row -> 4 per thread
            const float* Af = (const float*)Aptr;
            #pragma unroll
            for (int i = 0; i < 4; ++i) {
                int u = tid + i * 256;
                int row = u >> 3, ch = u & 7;
                int grow = bm0 + row;
                int ok = (grow < M);
                const float* src = Af + (size_t)(ok ? grow : 0) * K + k0 + ch * 4;
                uint32_t dst = smem_u32((float*)As + row * (AF_LD * 2) + ch * 4);
                int nb = ok ? 16 : 0;
                asm volatile("cp.async.ca.shared.global [%0], [%1], 16, %2;"
                             :: "r"(dst), "l"(src), "r"(nb));
            }
        } else {
            // A: 128 rows x 32 halves; 4 chunks of 16B per row -> 2 per thread
            const unsigned short* Ah = (const unsigned short*)Aptr;
            #pragma unroll
            for (int i = 0; i < 2; ++i) {
                int u = tid + i * 256;
                int row = u >> 2, ch = u & 3;
                int grow = bm0 + row;
                int ok = (grow < M);
                const unsigned short* src = Ah + (size_t)(ok ? grow : 0) * K + k0 + ch * 8;
                uint32_t dst = smem_u32(&As[row * AH_LD + ch * 4]);
                int nb = ok ? 16 : 0;
                asm volatile("cp.async.ca.shared.global [%0], [%1], 16, %2;"
                             :: "r"(dst), "l"(src), "r"(nb));
            }
        }
        constexpr int BU = BN / 64;
        #pragma unroll
        for (int i = 0; i < BU; ++i) {
            int u = tid + i * 256;
            int row = u / (BN / 4);
            int col4 = (u % (BN / 4)) * 4;
            const unsigned int* src = Bp + (size_t)(k0 / 2 + row) * N + bn0 + col4;
            uint32_t dst = smem_u32(&Bs[row * BSH_LD + col4]);
            asm volatile("cp.async.ca.shared.global [%0], [%1], 16;"
                         :: "r"(dst), "l"(src));
        }
        asm volatile("cp.async.commit_group;");
    };

    load_stage(0, 0);

    for (int kt = 0; kt < nk; ++kt) {
        const int buf = kt & 1;
        if (kt + 1 < nk) load_stage(kt + 1, buf ^ 1);
        else asm volatile("cp.async.commit_group;");
        asm volatile("cp.async.wait_group 1;");
        __syncthreads();

        const unsigned int* as = AsBase + buf * A_STG;
        const float2* as2 = (const float2*)as;
        const unsigned int* bs = BsBase + buf * B_STG;
        #pragma unroll
        for (int kk = 0; kk < 2; ++kk) {       // 2 x k16
            const int kb2 = kk * 8;            // pair offset
            uint32_t afrag[4][4], bfrag[NT][2];
            #pragma unroll
            for (int mt = 0; mt < 4; ++mt) {
                int r0 = wm + mt * 16 + (lane >> 2);
                int c0 = kb2 + (lane & 3);
                if constexpr (AFP32) {
                    float2 v0 = as2[r0 * AF_LD + c0];
                    float2 v1 = as2[(r0 + 8) * AF_LD + c0];
                    float2 v2 = as2[r0 * AF_LD + c0 + 4];
                    float2 v3 = as2[(r0 + 8) * AF_LD + c0 + 4];
                    afrag[mt][0] = pack_h2(v0.x, v0.y);
                    afrag[mt][1] = pack_h2(v1.x, v1.y);
                    afrag[mt][2] = pack_h2(v2.x, v2.y);
                    afrag[mt][3] = pack_h2(v3.x, v3.y);
                } else {
                    afrag[mt][0] = as[r0 * AH_LD + c0];
                    afrag[mt][1] = as[(r0 + 8) * AH_LD + c0];
                    afrag[mt][2] = as[r0 * AH_LD + c0 + 4];
                    afrag[mt][3] = as[(r0 + 8) * AH_LD + c0 + 4];
                }
            }
            #pragma unroll
            for (int nt = 0; nt < NT; ++nt) {
                int n0 = wn + nt * 8 + (lane >> 2);
                int kr = kb2 + (lane & 3);
                bfrag[nt][0] = bs[kr * BSH_LD + n0];
                bfrag[nt][1] = bs[(kr + 4) * BSH_LD + n0];
            }
            #pragma unroll
            for (int mt = 0; mt < 4; ++mt)
                #pragma unroll
                for (int nt = 0; nt < NT; ++nt)
                    mma_fp16(acc[mt][nt], afrag[mt], bfrag[nt]);
        }
        __syncthreads();
    }

    // ---- store C as half2 pairs ----
    const int NH = N / 2;
    #pragma unroll
    for (int mt = 0; mt < 4; ++mt) {
        int row0 = bm0 + wm + mt * 16 + (lane >> 2);
        #pragma unroll
        for (int nt = 0; nt < NT; ++nt) {
            int cp = (bn0 + wn + nt * 8 + (lane & 3) * 2) >> 1;
            if (row0 < M)
                Ch[(size_t)row0 * NH + cp] = pack_h2(acc[mt][nt][0], acc[mt][nt][1]);
            if (row0 + 8 < M)
                Ch[(size_t)(row0 + 8) * NH + cp] = pack_h2(acc[mt][nt][2], acc[mt][nt][3]);
        }
    }

    // ---- fused attention-logit epilogues (fp32 accumulators) ----
    if constexpr (FUSE_MODE == 1) {
        float asv[NT][2], adv[NT][2];
        #pragma unroll
        for (int nt = 0; nt < NT; ++nt) {
            int col = bn0 + wn + nt * 8 + (lane & 3) * 2;
            asv[nt][0] = attn_s[col];     asv[nt][1] = attn_s[col + 1];
            adv[nt][0] = attn_d[col];     adv[nt][1] = attn_d[col + 1];
        }
        #pragma unroll
        for (int mt = 0; mt < 4; ++mt) {
            #pragma unroll
            for (int hh = 0; hh < NHEAD; ++hh) {
                float slo = 0.f, shi = 0.f, dlo = 0.f, dhi = 0.f;
                #pragma unroll
                for (int q = 0; q < 4; ++q) {
                    int nt = hh * 4 + q;
                    slo += acc[mt][nt][0] * asv[nt][0] + acc[mt][nt][1] * asv[nt][1];
                    shi += acc[mt][nt][2] * asv[nt][0] + acc[mt][nt][3] * asv[nt][1];
                    dlo += acc[mt][nt][0] * adv[nt][0] + acc[mt][nt][1] * adv[nt][1];
                    dhi += acc[mt][nt][2] * adv[nt][0] + acc[mt][nt][3] * adv[nt][1];
                }
                #pragma unroll
                for (int o = 1; o <= 2; o <<= 1) {
                    slo += __shfl_xor_sync(0xffffffffu, slo, o);
                    shi += __shfl_xor_sync(0xffffffffu, shi, o);
                    dlo += __shfl_xor_sync(0xffffffffu, dlo, o);
                    dhi += __shfl_xor_sync(0xffffffffu, dhi, o);
                }
                if ((lane & 3) == 0) {
                    int head = (bn0 + wn) / 32 + hh;
                    int row0 = bm0 + wm + mt * 16 + (lane >> 2);
                    if (row0 < M) {
                        out_als[row0 * 8 + head] = slo;
                        out_ald[row0 * 8 + head] = dlo;
                    }
                    if (row0 + 8 < M) {
                        out_als[(row0 + 8) * 8 + head] = shi;
                        out_ald[(row0 + 8) * 8 + head] = dhi;
                    }
                }
            }
        }
    }
    if constexpr (FUSE_MODE == 2) {
        float asv[NT][2], adv[NT][2];
        #pragma unroll
        for (int nt = 0; nt < NT; ++nt) {
            int col = bn0 + wn + nt * 8 + (lane & 3) * 2;
            asv[nt][0] = attn_s[col];     asv[nt][1] = attn_s[col + 1];
            adv[nt][0] = attn_d[col];     adv[nt][1] = attn_d[col + 1];
        }
        #pragma unroll
        for (int mt = 0; mt < 4; ++mt) {
            float slo = 0.f, shi = 0.f, dlo = 0.f, dhi = 0.f;
            #pragma unroll
            for (int nt = 0; nt < NT; ++nt) {
                slo += acc[mt][nt][0] * asv[nt][0] + acc[mt][nt][1] * asv[nt][1];
                shi += acc[mt][nt][2] * asv[nt][0] + acc[mt][nt][3] * asv[nt][1];
                dlo += acc[mt][nt][0] * adv[nt][0] + acc[mt][nt][1] * adv[nt][1];
                dhi += acc[mt][nt][2] * adv[nt][0] + acc[mt][nt][3] * adv[nt][1];
            }
            #pragma unroll
            for (int o = 1; o <= 2; o <<= 1) {
                slo += __shfl_xor_sync(0xffffffffu, slo, o);
                shi += __shfl_xor_sync(0xffffffffu, shi, o);
                dlo += __shfl_xor_sync(0xffffffffu, dlo, o);
                dhi += __shfl_xor_sync(0xffffffffu, dhi, o);
            }
            if ((lane & 3) == 0) {
                int row0 = bm0 + wm + mt * 16 + (lane >> 2);
                if (row0 < M) {
                    atomicAdd(&out_als[row0], slo);
                    atomicAdd(&out_ald[row0], dlo);
                }
                if (row0 + 8 < M) {
                    atomicAdd(&out_als[row0 + 8], shi);
                    atomicAdd(&out_ald[row0 + 8], dhi);
                }
            }
        }
    }
}

#define G1_SMEM ((2 * 128 * AF_LD * 2 + 2 * 16 * (256 + 8)) * 4)
#define G2_SMEM ((2 * 128 * AH_LD + 2 * 16 * (128 + 8)) * 4)

// ---------------- layer-1: warp-per-node softmax+aggregate+bias+LN+ELU -------------
__global__ void __launch_bounds__(256)
gat1_warp_kernel(const float* __restrict__ b, const float* __restrict__ g,
                 const float* __restrict__ beta, int Nn) {
    __shared__ float sh_rae[48];
    const int t = threadIdx.x;
    if (t < 48) sh_rae[t] = g_rae[t];
    __syncthreads();

    const int d = blockIdx.x * 8 + (t >> 5);
    if (d >= Nn) return;
    const int lane = t & 31;
    const int hl = lane >> 2;

    const int beg = g_off[d], end = g_off[d + 1];
    const float aldl = g_ald1[d * 8 + hl];

    float acc[8] = {0.f, 0.f, 0.f, 0.f, 0.f, 0.f, 0.f, 0.f};
    float den = 0.f, sumrae = 0.f;

    #pragma unroll 2
    for (int e = beg; e < end; ++e) {
        int p = g_csr_pack[e];
        int s = p & 0xFFFFF, r = p >> 20;
        float rv = sh_rae[r * 8 + hl];
        float a = g_als1[s * 8 + hl] + aldl + rv;
        a = a > 0.f ? a : 0.2f * a;
        float ex = __expf(a);
        den += ex;
        sumrae += rv;
        uint4 u = reinterpret_cast<const uint4*>(g_h1h + (size_t)s * 128)[lane];
        float2 f0 = __half22float2(*reinterpret_cast<__half2*>(&u.x));
        float2 f1 = __half22float2(*reinterpret_cast<__half2*>(&u.y));
        float2 f2 = __half22float2(*reinterpret_cast<__half2*>(&u.z));
        float2 f3 = __half22float2(*reinterpret_cast<__half2*>(&u.w));
        acc[0] += ex * f0.x; acc[1] += ex * f0.y;
        acc[2] += ex * f1.x; acc[3] += ex * f1.y;
        acc[4] += ex * f2.x; acc[5] += ex * f2.y;
        acc[6] += ex * f3.x; acc[7] += ex * f3.y;
    }

    float deg = (float)(end - beg);
    float asf = g_als1[d * 8 + hl] + aldl + sumrae / fmaxf(deg, 1.f);
    asf = asf > 0.f ? asf : 0.2f * asf;
    float exs = __expf(asf);
    den += exs;
    {
        uint4 u = reinterpret_cast<const uint4*>(g_h1h + (size_t)d * 128)[lane];
        float2 f0 = __half22float2(*reinterpret_cast<__half2*>(&u.x));
        float2 f1 = __half22float2(*reinterpret_cast<__half2*>(&u.y));
        float2 f2 = __half22float2(*reinterpret_cast<__half2*>(&u.z));
        float2 f3 = __half22float2(*reinterpret_cast<__half2*>(&u.w));
        acc[0] += exs * f0.x; acc[1] += exs * f0.y;
        acc[2] += exs * f1.x; acc[3] += exs * f1.y;
        acc[4] += exs * f2.x; acc[5] += exs * f2.y;
        acc[6] += exs * f3.x; acc[7] += exs * f3.y;
    }

    float inv = 1.f / (den + 1e-16f);
    const float4* bp = reinterpret_cast<const float4*>(b);
    float4 b0 = bp[lane * 2], b1 = bp[lane * 2 + 1];
    float v[8];
    v[0] = acc[0] * inv + b0.x; v[1] = acc[1] * inv + b0.y;
    v[2] = acc[2] * inv + b0.z; v[3] = acc[3] * inv + b0.w;
    v[4] = acc[4] * inv + b1.x; v[5] = acc[5] * inv + b1.y;
    v[6] = acc[6] * inv + b1.z; v[7] = acc[7] * inv + b1.w;

    float s1 = 0.f, s2 = 0.f;
    #pragma unroll
    for (int k = 0; k < 8; ++k) { s1 += v[k]; s2 += v[k] * v[k]; }
    #pragma unroll
    for (int o = 16; o; o >>= 1) {
        s1 += __shfl_xor_sync(0xffffffffu, s1, o);
        s2 += __shfl_xor_sync(0xffffffffu, s2, o);
    }
    float m = s1 * (1.f / 256.f);
    float var = s2 * (1.f / 256.f) - m * m;
    float rstd = rsqrtf(var + 1e-5f);

    const float4* gp = reinterpret_cast<const float4*>(g);
    const float4* betap = reinterpret_cast<const float4*>(beta);
    float4 g0 = gp[lane * 2], g1v = gp[lane * 2 + 1];
    float4 be0 = betap[lane * 2], be1 = betap[lane * 2 + 1];
    float gg[8] = {g0.x, g0.y, g0.z, g0.w, g1v.x, g1v.y, g1v.z, g1v.w};
    float bb[8] = {be0.x, be0.y, be0.z, be0.w, be1.x, be1.y, be1.z, be1.w};
    float y[8];
    #pragma unroll
    for (int k = 0; k < 8; ++k) {
        float yy = (v[k] - m) * rstd * gg[k] + bb[k];
        y[k] = yy > 0.f ? yy : expm1f(yy);
    }
    uint4 o4;
    o4.x = pack_h2(y[0], y[1]);
    o4.y = pack_h2(y[2], y[3]);
    o4.z = pack_h2(y[4], y[5]);
    o4.w = pack_h2(y[6], y[7]);
    reinterpret_cast<uint4*>(g_out1h + (size_t)d * 128)[lane] = o4;
}

// ---------------- layer-2: warp-per-node softmax+aggregate+bias+LN -----------------
__global__ void __launch_bounds__(256)
gat2_warp_kernel(const float* __restrict__ b, const float* __restrict__ g,
                 const float* __restrict__ beta, float* __restrict__ out, int Nn) {
    const int t = threadIdx.x;
    const int d = blockIdx.x * 8 + (t >> 5);
    if (d >= Nn) return;
    const int lane = t & 31;

    const int beg = g_off[d], end = g_off[d + 1];
    const float ald = g_ald2[d];

    float acc[4] = {0.f, 0.f, 0.f, 0.f};
    float den = 0.f;

    #pragma unroll 2
    for (int e = beg; e < end; ++e) {
        int s = g_csr_pack[e] & 0xFFFFF;
        float a = g_als2[s] + ald;
        a = a > 0.f ? a : 0.2f * a;
        float ex = __expf(a);
        den += ex;
        uint2 u = reinterpret_cast<const uint2*>(g_h2h + (size_t)s * 64)[lane];
        float2 f0 = __half22float2(*reinterpret_cast<__half2*>(&u.x));
        float2 f1 = __half22float2(*reinterpret_cast<__half2*>(&u.y));
        acc[0] += ex * f0.x; acc[1] += ex * f0.y;
        acc[2] += ex * f1.x; acc[3] += ex * f1.y;
    }

    float asf = g_als2[d] + ald;
    asf = asf > 0.f ? asf : 0.2f * asf;
    float exs = __expf(asf);
    den += exs;
    {
        uint2 u = reinterpret_cast<const uint2*>(g_h2h + (size_t)d * 64)[lane];
        float2 f0 = __half22float2(*reinterpret_cast<__half2*>(&u.x));
        float2 f1 = __half22float2(*reinterpret_cast<__half2*>(&u.y));
        acc[0] += exs * f0.x; acc[1] += exs * f0.y;
        acc[2] += exs * f1.x; acc[3] += exs * f1.y;
    }

    float inv = 1.f / (den + 1e-16f);
    float4 bv = reinterpret_cast<const float4*>(b)[lane];
    float v[4];
    v[0] = acc[0] * inv + bv.x; v[1] = acc[1] * inv + bv.y;
    v[2] = acc[2] * inv + bv.z; v[3] = acc[3] * inv + bv.w;

    float s1 = 0.f, s2 = 0.f;
    #pragma unroll
    for (int k = 0; k < 4; ++k) { s1 += v[k]; s2 += v[k] * v[k]; }
    #pragma unroll
    for (int o = 16; o; o >>= 1) {
        s1 += __shfl_xor_sync(0xffffffffu, s1, o);
        s2 += __shfl_xor_sync(0xffffffffu, s2, o);
    }
    float m = s1 * (1.f / 128.f);
    float var = s2 * (1.f / 128.f) - m * m;
    float rstd = rsqrtf(var + 1e-5f);

    float4 gv = reinterpret_cast<const float4*>(g)[lane];
    float4 bev = reinterpret_cast<const float4*>(beta)[lane];
    float4 o4;
    o4.x = (v[0] - m) * rstd * gv.x + bev.x;
    o4.y = (v[1] - m) * rstd * gv.y + bev.y;
    o4.z = (v[2] - m) * rstd * gv.z + bev.z;
    o4.w = (v[3] - m) * rstd * gv.w + bev.w;
    reinterpret_cast<float4*>(out + (size_t)d * 128)[lane] = o4;
}

// ---------------- launch -------------------------------------------------------------
extern "C" void kernel_launch(void* const* d_in, const int* in_sizes, int n_in,
                              void* d_out, int out_size) {
    const float* x       = (const float*)d_in[0];
    const int*   ei      = (const int*)d_in[1];
    const int*   etype   = (const int*)d_in[2];
    const float* rel_emb = (const float*)d_in[3];
    const float* W1      = (const float*)d_in[4];
    const float* as1     = (const float*)d_in[5];
    const float* ad1     = (const float*)d_in[6];
    const float* We1     = (const float*)d_in[7];
    const float* ae1     = (const float*)d_in[8];
    const float* b1      = (const float*)d_in[9];
    const float* g1      = (const float*)d_in[10];
    const float* beta1   = (const float*)d_in[11];
    const float* W2      = (const float*)d_in[12];
    const float* as2     = (const float*)d_in[13];
    const float* ad2     = (const float*)d_in[14];
    const float* b2      = (const float*)d_in[15];
    const float* g2      = (const float*)d_in[16];
    const float* beta2   = (const float*)d_in[17];
    float* out = (float*)d_out;

    const int E = in_sizes[2];
    const int Nn = in_sizes[0] / 768;
    const int* src0 = ei;
    const int* dst0 = ei + E;
    const int nb = (Nn + 1023) / 1024;
    const int nm = (Nn + 127) / 128;

    float *pals1, *pald1, *pals2, *pald2;
    unsigned int *pw1p, *pw2p, *ph1h, *pout1h, *ph2h;
    cudaGetSymbolAddress((void**)&pw1p, g_w1p);
    cudaGetSymbolAddress((void**)&pw2p, g_w2p);
    cudaGetSymbolAddress((void**)&ph1h, g_h1h);
    cudaGetSymbolAddress((void**)&pout1h, g_out1h);
    cudaGetSymbolAddress((void**)&ph2h, g_h2h);
    cudaGetSymbolAddress((void**)&pals1, g_als1);
    cudaGetSymbolAddress((void**)&pald1, g_ald1);
    cudaGetSymbolAddress((void**)&pals2, g_als2);
    cudaGetSymbolAddress((void**)&pald2, g_ald2);

    static cudaStream_t s_side = nullptr;
    static cudaEvent_t ev_fork = nullptr, ev_join = nullptr;
    if (!s_side) {
        cudaFuncSetAttribute(gemm_fp16_kernel<256, 1, true>,
                             cudaFuncAttributeMaxDynamicSharedMemorySize, G1_SMEM);
        cudaFuncSetAttribute(gemm_fp16_kernel<128, 2, false>,
                             cudaFuncAttributeMaxDynamicSharedMemorySize, G2_SMEM);
        cudaStreamCreateWithFlags(&s_side, cudaStreamNonBlocking);
        cudaEventCreateWithFlags(&ev_fork, cudaEventDisableTiming);
        cudaEventCreateWithFlags(&ev_join, cudaEventDisableTiming);
    }

    // ---- fork: CSR build + prep + W2 pack on side stream ----
    cudaEventRecord(ev_fork, 0);
    cudaStreamWaitEvent(s_side, ev_fork, 0);

    init_kernel<<<(Nn + 255) / 256, 256, 0, s_side>>>(Nn);
    prep_kernel<<<1, 512, 0, s_side>>>(We1, ae1, rel_emb);
    hist_kernel<<<(E + 255) / 256, 256, 0, s_side>>>(dst0, E);
    scan_part_kernel<<<nb, 1024, 0, s_side>>>(Nn);
    scan_tops_kernel<<<1, 64, 0, s_side>>>(nb);
    scan_add_kernel<<<(Nn + 255) / 256, 256, 0, s_side>>>(Nn, E);
    scatter_kernel<<<(E + 255) / 256, 256, 0, s_side>>>(src0, dst0, etype, E);
    pack_w_kernel<<<(128 * 128 + 255) / 256, 256, 0, s_side>>>(W2, pw2p, 256, 128);
    cudaEventRecord(ev_join, s_side);

    // ---- main: pack W1, then fp16 GEMM1 reading fp32 x directly ----
    pack_w_kernel<<<(384 * 256 + 255) / 256, 256>>>(W1, pw1p, 768, 256);
    {
        dim3 grid(1, nm);
        gemm_fp16_kernel<256, 1, true><<<grid, 256, G1_SMEM>>>(
            x, pw1p, ph1h, Nn, 256, 768, as1, ad1, pals1, pald1);
    }

    // ---- join ----
    cudaStreamWaitEvent(0, ev_join, 0);

    gat1_warp_kernel<<<(Nn + 7) / 8, 256>>>(b1, g1, beta1, Nn);

    // GEMM2: h2 = out1 @ W2 (fp16 A), fused attn2
    {
        dim3 grid(1, nm);
        gemm_fp16_kernel<128, 2, false><<<grid, 256, G2_SMEM>>>(
            pout1h, pw2p, ph2h, Nn, 128, 256, as2, ad2, pals2, pald2);
    }
    gat2_warp_kernel<<<(Nn + 7) / 8, 256>>>(b2, g2, beta2, out, Nn);
}